// round 7
// baseline (speedup 1.0000x reference)
#include <cuda_runtime.h>
#include <cstdint>

#define NE 100000
#define NN 10000
#define KW 1024
#define N3 4096

// ---- static device scratch (no allocations allowed) ----
__device__ float g_r1[(size_t)NE * KW];    // relu1  [E,1024]  (tf32-rounded)
__device__ float g_r2[(size_t)NE * KW];    // relu2  [E,1024]  (tf32-rounded)
__device__ float g_W[(size_t)NE * N3];     // W_edge [E,64,64] fp32
__device__ float g_k2r[(size_t)KW * KW];   // tf32-rounded k2_w
__device__ float g_k3r[(size_t)KW * N3];   // tf32-rounded k3_w
__device__ float g_hA[NN * 64];
__device__ float g_hB[NN * 64];
__device__ float g_agg[NN * 64];
__device__ float g_inv[NN];

__device__ __forceinline__ float tf32r(float x) {
    uint32_t u;
    asm("cvt.rna.tf32.f32 %0, %1;" : "=r"(u) : "f"(x));
    return __uint_as_float(u);
}

__device__ __forceinline__ void mma_tf32(float* d, const uint32_t* a, const uint32_t* b) {
    asm volatile(
        "mma.sync.aligned.m16n8k8.row.col.f32.tf32.tf32.f32 "
        "{%0,%1,%2,%3}, {%4,%5,%6,%7}, {%8,%9}, {%0,%1,%2,%3};\n"
        : "+f"(d[0]), "+f"(d[1]), "+f"(d[2]), "+f"(d[3])
        : "r"(a[0]), "r"(a[1]), "r"(a[2]), "r"(a[3]), "r"(b[0]), "r"(b[1]));
}

// ---- tf32 round-copy of weights ----
__global__ void k_round(const float* __restrict__ in, float* __restrict__ out, int n) {
    int i = blockIdx.x * 256 + threadIdx.x;
    if (i < n) out[i] = tf32r(in[i]);
}

// ---- layer 1 of edge MLP: [E,6] @ [6,1024] + b, relu, tf32-round ----
__global__ void k_mlp1(const float* __restrict__ ea, const float* __restrict__ w,
                       const float* __restrict__ b, float* __restrict__ out) {
    int idx = blockIdx.x * 256 + threadIdx.x;   // grid is exactly E*1024/256
    int e = idx >> 10, n = idx & 1023;
    const float* a = ea + e * 6;
    float s = b[n];
#pragma unroll
    for (int j = 0; j < 6; j++) s = fmaf(a[j], w[j * KW + n], s);
    out[idx] = tf32r(fmaxf(s, 0.f));
}

// ---- tf32 tensor-core GEMM: C[M,N] = A[M,K] @ B[K,N] + bias ----
// BM=128 BN=128 BK=16, 256 threads = 8 warps (4 in M x 2 in N), warp tile 32x64.
// A,B pre-rounded to tf32 so raw f32 bits == exact tf32 operands.
// mode 1: relu + tf32-round epilogue (feeds next GEMM).  mode 0: bias only.
__global__ __launch_bounds__(256, 2)
void k_gemm(const float* __restrict__ A, const float* __restrict__ B,
            const float* __restrict__ bias, float* __restrict__ C,
            int M, int N, int K, int mode) {
    __shared__ __align__(16) float As[2][128][20];   // pad 16->20: conflict-free frag lds
    __shared__ __align__(16) float Bs[2][16][132];   // pad 128->132

    const int tid = threadIdx.x;
    const int warp = tid >> 5, lane = tid & 31;
    const int wm = warp & 3, wn = warp >> 2;
    const int g = lane >> 2, t = lane & 3;
    const int bM = blockIdx.x, bN = blockIdx.y;

    const float* Ablk = A + (size_t)bM * 128 * K;
    const float* Bblk = B + (size_t)bN * 128;

    float acc[2][8][4];
#pragma unroll
    for (int i = 0; i < 2; i++)
#pragma unroll
        for (int j = 0; j < 8; j++)
#pragma unroll
            for (int q = 0; q < 4; q++) acc[i][j][q] = 0.f;

    auto loadTiles = [&](int kb, int buf) {
        int k0 = kb * 16;
#pragma unroll
        for (int i = 0; i < 2; i++) {   // A tile: 128x16 = 512 x 16B chunks
            int c = tid + i * 256;
            int ar = c >> 2, ac = (c & 3) * 4;
            const float* src = Ablk + (size_t)ar * K + k0 + ac;
            int pred = (bM * 128 + ar < M) ? 16 : 0;
            uint32_t da = (uint32_t)__cvta_generic_to_shared(&As[buf][ar][ac]);
            asm volatile("cp.async.ca.shared.global [%0], [%1], 16, %2;\n"
                         :: "r"(da), "l"(src), "r"(pred));
        }
#pragma unroll
        for (int i = 0; i < 2; i++) {   // B tile: 16x128 = 512 x 16B chunks
            int c = tid + i * 256;
            int br = c >> 5, bc = (c & 31) * 4;
            const float* src = Bblk + (size_t)(k0 + br) * N + bc;
            uint32_t da = (uint32_t)__cvta_generic_to_shared(&Bs[buf][br][bc]);
            asm volatile("cp.async.ca.shared.global [%0], [%1], 16;\n"
                         :: "r"(da), "l"(src));
        }
        asm volatile("cp.async.commit_group;\n");
    };

    const int NKB = K / 16;
    loadTiles(0, 0);
    int buf = 0;
    for (int kb = 0; kb < NKB; kb++) {
        asm volatile("cp.async.wait_group 0;\n");
        __syncthreads();
        if (kb + 1 < NKB) loadTiles(kb + 1, buf ^ 1);
#pragma unroll
        for (int ks = 0; ks < 2; ks++) {
            uint32_t afr[2][4], bfr[8][2];
#pragma unroll
            for (int mt = 0; mt < 2; mt++) {
                int r = wm * 32 + mt * 16;
                int cc = ks * 8;
                afr[mt][0] = __float_as_uint(As[buf][r + g][cc + t]);
                afr[mt][1] = __float_as_uint(As[buf][r + g + 8][cc + t]);
                afr[mt][2] = __float_as_uint(As[buf][r + g][cc + t + 4]);
                afr[mt][3] = __float_as_uint(As[buf][r + g + 8][cc + t + 4]);
            }
#pragma unroll
            for (int nt = 0; nt < 8; nt++) {
                int cn = wn * 64 + nt * 8 + g;
                bfr[nt][0] = __float_as_uint(Bs[buf][ks * 8 + t][cn]);
                bfr[nt][1] = __float_as_uint(Bs[buf][ks * 8 + t + 4][cn]);
            }
#pragma unroll
            for (int mt = 0; mt < 2; mt++)
#pragma unroll
                for (int nt = 0; nt < 8; nt++)
                    mma_tf32(acc[mt][nt], afr[mt], bfr[nt]);
        }
        __syncthreads();
        buf ^= 1;
    }

    // epilogue
#pragma unroll
    for (int mt = 0; mt < 2; mt++) {
#pragma unroll
        for (int nt = 0; nt < 8; nt++) {
            int col = bN * 128 + wn * 64 + nt * 8 + 2 * t;
            float b0 = bias[col], b1 = bias[col + 1];
            int r0 = bM * 128 + wm * 32 + mt * 16 + g;
            int r1 = r0 + 8;
            float v0 = acc[mt][nt][0] + b0, v1 = acc[mt][nt][1] + b1;
            float v2 = acc[mt][nt][2] + b0, v3 = acc[mt][nt][3] + b1;
            if (mode == 1) {
                v0 = tf32r(fmaxf(v0, 0.f)); v1 = tf32r(fmaxf(v1, 0.f));
                v2 = tf32r(fmaxf(v2, 0.f)); v3 = tf32r(fmaxf(v3, 0.f));
            }
            if (r0 < M) *(float2*)(C + (size_t)r0 * N + col) = make_float2(v0, v1);
            if (r1 < M) *(float2*)(C + (size_t)r1 * N + col) = make_float2(v2, v3);
        }
    }
}

// ---- in-degree via atomics (edge_index is int32: JAX silently downcasts int64) ----
__global__ void k_deg(const int* __restrict__ ei, float* __restrict__ deg) {
    int i = blockIdx.x * 256 + threadIdx.x;
    if (i < NE) atomicAdd(&deg[ei[NE + i]], 1.f);
}
__global__ void k_inv(float* __restrict__ deg) {
    int n = blockIdx.x * 256 + threadIdx.x;
    if (n < NN) { float d = deg[n]; deg[n] = (d > 0.f) ? (1.f / d) : 0.f; }
}

// ---- h0 = x @ fc1_w + fc1_b   (IN_WIDTH = 1) ----
__global__ void k_h0(const float* __restrict__ x, const float* __restrict__ w,
                     const float* __restrict__ b, float* __restrict__ h) {
    int idx = blockIdx.x * 256 + threadIdx.x;   // NN*64 exact
    int n = idx >> 6, o = idx & 63;
    h[idx] = fmaf(x[n], w[o], b[o]);
}

// ---- per-edge matvec + scatter-add: one warp per edge, float2 per lane ----
__global__ __launch_bounds__(256)
void k_edge(const float* __restrict__ h, const float* __restrict__ W,
            const int* __restrict__ ei, float* __restrict__ agg) {
    int warp = threadIdx.x >> 5, lane = threadIdx.x & 31;
    int e = blockIdx.x * 8 + warp;             // NE divisible by 8
    int src = ei[e], dst = ei[NE + e];
    __shared__ float sh[8][64];
    float2 hv = ((const float2*)(h + (size_t)src * 64))[lane];
    sh[warp][2 * lane] = hv.x;
    sh[warp][2 * lane + 1] = hv.y;
    __syncwarp();
    const float2* Wr = (const float2*)(W + (size_t)e * 4096);
    float m0 = 0.f, m1 = 0.f;
#pragma unroll 16
    for (int c = 0; c < 64; c++) {
        float hc = sh[warp][c];
        float2 w = __ldg(&Wr[c * 32 + lane]);
        m0 = fmaf(hc, w.x, m0);
        m1 = fmaf(hc, w.y, m1);
    }
    atomicAdd(&agg[dst * 64 + 2 * lane], m0);
    atomicAdd(&agg[dst * 64 + 2 * lane + 1], m1);
}

// ---- h_new = agg*inv_deg + h@root + conv_b (+relu) ----
__global__ void k_update(const float* __restrict__ hin, const float* __restrict__ agg,
                         const float* __restrict__ inv, const float* __restrict__ root,
                         const float* __restrict__ cb, float* __restrict__ hout, int relu) {
    int ni = threadIdx.x >> 6;
    int node = blockIdx.x * 4 + ni;            // NN divisible by 4
    int o = threadIdx.x & 63;
    __shared__ float sh[4][64];
    sh[ni][o] = hin[node * 64 + o];
    __syncthreads();
    float acc = fmaf(agg[node * 64 + o], inv[node], cb[o]);
#pragma unroll
    for (int c = 0; c < 64; c++) acc = fmaf(sh[ni][c], root[c * 64 + o], acc);
    if (relu) acc = fmaxf(acc, 0.f);
    hout[node * 64 + o] = acc;
}

// ---- out = h @ fc2_w + fc2_b : one warp per node ----
__global__ void k_final(const float* __restrict__ h, const float* __restrict__ w,
                        const float* __restrict__ b, float* __restrict__ out) {
    int node = blockIdx.x * 8 + (threadIdx.x >> 5);  // NN divisible by 8
    int lane = threadIdx.x & 31;
    float v = h[node * 64 + lane] * w[lane] + h[node * 64 + 32 + lane] * w[32 + lane];
#pragma unroll
    for (int s = 16; s > 0; s >>= 1) v += __shfl_xor_sync(0xffffffffu, v, s);
    if (lane == 0) out[node] = v + b[0];
}

extern "C" void kernel_launch(void* const* d_in, const int* in_sizes, int n_in,
                              void* d_out, int out_size) {
    const float* x    = (const float*)d_in[0];
    const int*   ei   = (const int*)d_in[1];     // int32 (JAX downcasts int64)
    const float* ea   = (const float*)d_in[2];
    const float* fc1w = (const float*)d_in[3];
    const float* fc1b = (const float*)d_in[4];
    const float* k1w  = (const float*)d_in[5];
    const float* k1b  = (const float*)d_in[6];
    const float* k2w  = (const float*)d_in[7];
    const float* k2b  = (const float*)d_in[8];
    const float* k3w  = (const float*)d_in[9];
    const float* k3b  = (const float*)d_in[10];
    const float* root = (const float*)d_in[11];
    const float* cb   = (const float*)d_in[12];
    const float* fc2w = (const float*)d_in[13];
    const float* fc2b = (const float*)d_in[14];
    float* out = (float*)d_out;

    float *r1, *r2, *Wd, *k2r, *k3r, *hA, *hB, *agg, *inv;
    cudaGetSymbolAddress((void**)&r1,  g_r1);
    cudaGetSymbolAddress((void**)&r2,  g_r2);
    cudaGetSymbolAddress((void**)&Wd,  g_W);
    cudaGetSymbolAddress((void**)&k2r, g_k2r);
    cudaGetSymbolAddress((void**)&k3r, g_k3r);
    cudaGetSymbolAddress((void**)&hA,  g_hA);
    cudaGetSymbolAddress((void**)&hB,  g_hB);
    cudaGetSymbolAddress((void**)&agg, g_agg);
    cudaGetSymbolAddress((void**)&inv, g_inv);

    // tf32-round weights once per launch
    k_round<<<(KW * KW + 255) / 256, 256>>>(k2w, k2r, KW * KW);
    k_round<<<(KW * N3 + 255) / 256, 256>>>(k3w, k3r, KW * N3);

    // edge MLP
    k_mlp1<<<NE * 4, 256>>>(ea, k1w, k1b, r1);
    dim3 g2((NE + 127) / 128, KW / 128);
    dim3 g3((NE + 127) / 128, N3 / 128);
    k_gemm<<<g2, 256>>>(r1, k2r, k2b, r2, NE, KW, KW, 1);
    k_gemm<<<g3, 256>>>(r2, k3r, k3b, Wd, NE, N3, KW, 0);

    // degrees
    cudaMemsetAsync(inv, 0, NN * sizeof(float));
    k_deg<<<(NE + 255) / 256, 256>>>(ei, inv);
    k_inv<<<(NN + 255) / 256, 256>>>(inv);

    // initial features
    k_h0<<<(NN * 64) / 256, 256>>>(x, fc1w, fc1b, hA);

    float* hc = hA;
    float* hn = hB;
    for (int d = 0; d < 6; d++) {
        cudaMemsetAsync(agg, 0, (size_t)NN * 64 * sizeof(float));
        k_edge<<<NE / 8, 256>>>(hc, Wd, ei, agg);
        k_update<<<NN / 4, 256>>>(hc, agg, inv, root, cb, hn, d < 5 ? 1 : 0);
        float* tmp = hc; hc = hn; hn = tmp;
    }

    k_final<<<NN / 8, 256>>>(hc, fc2w, fc2b, out);
}

// round 9
// speedup vs baseline: 1.5359x; 1.5359x over previous
#include <cuda_runtime.h>
#include <cstdint>

#define NE 100000
#define NN 10000
#define KW 1024
#define N3 4096

// ---- static device scratch (no allocations allowed) ----
__device__ float g_r1[(size_t)NE * KW];    // relu1  [E,1024]  tf32, K-permuted layout
__device__ float g_r2[(size_t)NE * KW];    // relu2  [E,1024]  tf32, K-permuted layout
__device__ float g_W[(size_t)NE * N3];     // W_edge [E,64,64] fp32 (normal layout)
__device__ float g_Bp2[(size_t)KW * KW];   // k2_w transposed [N,K], tf32, K-permuted
__device__ float g_Bp3[(size_t)N3 * KW];   // k3_w transposed [N,K], tf32, K-permuted
__device__ float g_hA[NN * 64];
__device__ float g_hB[NN * 64];
__device__ float g_agg[NN * 64];
__device__ float g_inv[NN];

__device__ __forceinline__ float tf32r(float x) {
    uint32_t u;
    asm("cvt.rna.tf32.f32 %0, %1;" : "=r"(u) : "f"(x));
    return __uint_as_float(u);
}

// permute k within each 16-group so a thread's 4 fragment elements are contiguous:
// position p = 4*(k&3) + ((k&15)>>2); chunk j holds k = {j, j+4, j+8, j+12}
__device__ __forceinline__ int permk(int k) {
    return (k & ~15) | (((k & 3) << 2) | ((k & 15) >> 2));
}

__device__ __forceinline__ void mma_tf32(float* d, const uint32_t* a, const uint32_t* b) {
    asm volatile(
        "mma.sync.aligned.m16n8k8.row.col.f32.tf32.tf32.f32 "
        "{%0,%1,%2,%3}, {%4,%5,%6,%7}, {%8,%9}, {%0,%1,%2,%3};\n"
        : "+f"(d[0]), "+f"(d[1]), "+f"(d[2]), "+f"(d[3])
        : "r"(a[0]), "r"(a[1]), "r"(a[2]), "r"(a[3]), "r"(b[0]), "r"(b[1]));
}

// ---- B prep: transpose [K,N] -> [N,K] with tf32 round + K-permute ----
__global__ void k_prepB(const float* __restrict__ in, float* __restrict__ out, int N) {
    __shared__ float tile[32][33];
    int nb = blockIdx.x * 32, kb = blockIdx.y * 32;
    for (int i = threadIdx.y; i < 32; i += 8)
        tile[i][threadIdx.x] = in[(size_t)(kb + i) * N + nb + threadIdx.x];
    __syncthreads();
    for (int i = threadIdx.y; i < 32; i += 8) {
        int n = nb + i, k = kb + threadIdx.x;
        out[(size_t)n * KW + permk(k)] = tf32r(tile[threadIdx.x][i]);
    }
}

// ---- layer 1 of edge MLP: [E,6] @ [6,1024] + b, relu, tf32-round, permuted write ----
__global__ void k_mlp1(const float* __restrict__ ea, const float* __restrict__ w,
                       const float* __restrict__ b, float* __restrict__ out) {
    int idx = blockIdx.x * 256 + threadIdx.x;   // grid is exactly E*1024/256
    int e = idx >> 10, n = idx & 1023;
    const float* a = ea + e * 6;
    float s = b[n];
#pragma unroll
    for (int j = 0; j < 6; j++) s = fmaf(a[j], w[j * KW + n], s);
    out[e * KW + permk(n)] = tf32r(fmaxf(s, 0.f));
}

// ---- tf32 tensor-core GEMM: C[M,N] = A[M,K] @ Bt[N,K]^T + bias ----
// A: [M,K] K-permuted. B: [N,K] K-permuted.  BM=BN=128, BK=16, 3-stage cp.async.
// Grid: x = N-blocks (fast, for A reuse in L2), y = M-blocks.
// mode 1: relu + tf32-round, permuted write (feeds next GEMM). mode 0: bias only, normal.
__global__ __launch_bounds__(256, 2)
void k_gemm(const float* __restrict__ A, const float* __restrict__ B,
            const float* __restrict__ bias, float* __restrict__ C,
            int M, int N, int K, int mode) {
    __shared__ __align__(16) float As[3][128][16];   // 3 x 8KB
    __shared__ __align__(16) float Bs[3][128][16];   // 3 x 8KB (total 48KB)

    const int tid = threadIdx.x;
    const int warp = tid >> 5, lane = tid & 31;
    const int wm = warp & 3, wn = warp >> 2;
    const int g = lane >> 2, t = lane & 3;
    const int bN = blockIdx.x, bM = blockIdx.y;

    const float* Ablk = A + (size_t)bM * 128 * K;
    const float* Bblk = B + (size_t)bN * 128 * K;

    float acc[2][8][4];
#pragma unroll
    for (int i = 0; i < 2; i++)
#pragma unroll
        for (int j = 0; j < 8; j++)
#pragma unroll
            for (int q = 0; q < 4; q++) acc[i][j][q] = 0.f;

    auto loadTiles = [&](int kb, int buf) {
        int k0 = kb * 16;
#pragma unroll
        for (int i = 0; i < 2; i++) {   // A: 128 rows x 4 chunks = 512 x 16B
            int c = tid + i * 256;
            int row = c >> 2, j = c & 3;
            const float* src = Ablk + (size_t)row * K + k0 + j * 4;
            int pr = (bM * 128 + row < M) ? 16 : 0;
            uint32_t da = (uint32_t)__cvta_generic_to_shared(&As[buf][row][j * 4]);
            asm volatile("cp.async.ca.shared.global [%0], [%1], 16, %2;\n"
                         :: "r"(da), "l"(src), "r"(pr));
        }
#pragma unroll
        for (int i = 0; i < 2; i++) {   // B: 128 rows x 4 chunks = 512 x 16B
            int c = tid + i * 256;
            int row = c >> 2, j = c & 3;
            const float* src = Bblk + (size_t)row * K + k0 + j * 4;
            uint32_t da = (uint32_t)__cvta_generic_to_shared(&Bs[buf][row][j * 4]);
            asm volatile("cp.async.ca.shared.global [%0], [%1], 16;\n"
                         :: "r"(da), "l"(src));
        }
        asm volatile("cp.async.commit_group;\n");
    };

    const int NKB = K / 16;
    loadTiles(0, 0);
    loadTiles(1, 1);
    int buf = 0, nextbuf = 2;   // buffer that kb+2 will be loaded into
    for (int kb = 0; kb < NKB; kb++) {
        asm volatile("cp.async.wait_group 1;\n");
        __syncthreads();
        if (kb + 2 < NKB) loadTiles(kb + 2, nextbuf);

        // A fragments: one float4 per (mt, row-half) covers both ks steps
        float4 av[2][2];
#pragma unroll
        for (int mt = 0; mt < 2; mt++) {
            int r = wm * 32 + mt * 16;
            av[mt][0] = *(const float4*)&As[buf][r + g][4 * t];
            av[mt][1] = *(const float4*)&As[buf][r + g + 8][4 * t];
        }
#pragma unroll
        for (int nt = 0; nt < 8; nt++) {
            int cn = wn * 64 + nt * 8 + g;
            float4 bv = *(const float4*)&Bs[buf][cn][4 * t];
            uint32_t b0[2] = { __float_as_uint(bv.x), __float_as_uint(bv.y) };  // ks=0
            uint32_t b1[2] = { __float_as_uint(bv.z), __float_as_uint(bv.w) };  // ks=1
#pragma unroll
            for (int mt = 0; mt < 2; mt++) {
                uint32_t a0[4] = { __float_as_uint(av[mt][0].x), __float_as_uint(av[mt][1].x),
                                   __float_as_uint(av[mt][0].y), __float_as_uint(av[mt][1].y) };
                uint32_t a1[4] = { __float_as_uint(av[mt][0].z), __float_as_uint(av[mt][1].z),
                                   __float_as_uint(av[mt][0].w), __float_as_uint(av[mt][1].w) };
                mma_tf32(acc[mt][nt], a0, b0);
                mma_tf32(acc[mt][nt], a1, b1);
            }
        }
        buf = (buf == 2) ? 0 : buf + 1;
        nextbuf = (nextbuf == 2) ? 0 : nextbuf + 1;
    }

    // epilogue
#pragma unroll
    for (int mt = 0; mt < 2; mt++) {
#pragma unroll
        for (int nt = 0; nt < 8; nt++) {
            int col = bN * 128 + wn * 64 + nt * 8 + 2 * t;
            float b0 = bias[col], b1 = bias[col + 1];
            int r0 = bM * 128 + wm * 32 + mt * 16 + g;
            int r1 = r0 + 8;
            float v0 = acc[mt][nt][0] + b0, v1 = acc[mt][nt][1] + b1;
            float v2 = acc[mt][nt][2] + b0, v3 = acc[mt][nt][3] + b1;
            if (mode == 1) {   // relu + tf32 round, K-permuted scalar stores
                v0 = tf32r(fmaxf(v0, 0.f)); v1 = tf32r(fmaxf(v1, 0.f));
                v2 = tf32r(fmaxf(v2, 0.f)); v3 = tf32r(fmaxf(v3, 0.f));
                int p0 = permk(col), p1 = permk(col + 1);
                if (r0 < M) { C[(size_t)r0 * N + p0] = v0; C[(size_t)r0 * N + p1] = v1; }
                if (r1 < M) { C[(size_t)r1 * N + p0] = v2; C[(size_t)r1 * N + p1] = v3; }
            } else {
                if (r0 < M) *(float2*)(C + (size_t)r0 * N + col) = make_float2(v0, v1);
                if (r1 < M) *(float2*)(C + (size_t)r1 * N + col) = make_float2(v2, v3);
            }
        }
    }
}

// ---- in-degree via atomics (edge_index is int32: JAX downcasts int64) ----
__global__ void k_deg(const int* __restrict__ ei, float* __restrict__ deg) {
    int i = blockIdx.x * 256 + threadIdx.x;
    if (i < NE) atomicAdd(&deg[ei[NE + i]], 1.f);
}
__global__ void k_inv(float* __restrict__ deg) {
    int n = blockIdx.x * 256 + threadIdx.x;
    if (n < NN) { float d = deg[n]; deg[n] = (d > 0.f) ? (1.f / d) : 0.f; }
}

// ---- h0 = x @ fc1_w + fc1_b   (IN_WIDTH = 1) ----
__global__ void k_h0(const float* __restrict__ x, const float* __restrict__ w,
                     const float* __restrict__ b, float* __restrict__ h) {
    int idx = blockIdx.x * 256 + threadIdx.x;   // NN*64 exact
    int n = idx >> 6, o = idx & 63;
    h[idx] = fmaf(x[n], w[o], b[o]);
}

// ---- per-edge matvec + scatter-add: one warp per edge, float2 per lane ----
__global__ __launch_bounds__(256)
void k_edge(const float* __restrict__ h, const float* __restrict__ W,
            const int* __restrict__ ei, float* __restrict__ agg) {
    int warp = threadIdx.x >> 5, lane = threadIdx.x & 31;
    int e = blockIdx.x * 8 + warp;             // NE divisible by 8
    int src = ei[e], dst = ei[NE + e];
    __shared__ float sh[8][64];
    float2 hv = ((const float2*)(h + (size_t)src * 64))[lane];
    sh[warp][2 * lane] = hv.x;
    sh[warp][2 * lane + 1] = hv.y;
    __syncwarp();
    const float2* Wr = (const float2*)(W + (size_t)e * 4096);
    float m0 = 0.f, m1 = 0.f;
#pragma unroll 16
    for (int c = 0; c < 64; c++) {
        float hc = sh[warp][c];
        float2 w = __ldg(&Wr[c * 32 + lane]);
        m0 = fmaf(hc, w.x, m0);
        m1 = fmaf(hc, w.y, m1);
    }
    atomicAdd(&agg[dst * 64 + 2 * lane], m0);
    atomicAdd(&agg[dst * 64 + 2 * lane + 1], m1);
}

// ---- h_new = agg*inv_deg + h@root + conv_b (+relu) ----
__global__ void k_update(const float* __restrict__ hin, const float* __restrict__ agg,
                         const float* __restrict__ inv, const float* __restrict__ root,
                         const float* __restrict__ cb, float* __restrict__ hout, int relu) {
    int ni = threadIdx.x >> 6;
    int node = blockIdx.x * 4 + ni;            // NN divisible by 4
    int o = threadIdx.x & 63;
    __shared__ float sh[4][64];
    sh[ni][o] = hin[node * 64 + o];
    __syncthreads();
    float acc = fmaf(agg[node * 64 + o], inv[node], cb[o]);
#pragma unroll
    for (int c = 0; c < 64; c++) acc = fmaf(sh[ni][c], root[c * 64 + o], acc);
    if (relu) acc = fmaxf(acc, 0.f);
    hout[node * 64 + o] = acc;
}

// ---- out = h @ fc2_w + fc2_b : one warp per node ----
__global__ void k_final(const float* __restrict__ h, const float* __restrict__ w,
                        const float* __restrict__ b, float* __restrict__ out) {
    int node = blockIdx.x * 8 + (threadIdx.x >> 5);  // NN divisible by 8
    int lane = threadIdx.x & 31;
    float v = h[node * 64 + lane] * w[lane] + h[node * 64 + 32 + lane] * w[32 + lane];
#pragma unroll
    for (int s = 16; s > 0; s >>= 1) v += __shfl_xor_sync(0xffffffffu, v, s);
    if (lane == 0) out[node] = v + b[0];
}

extern "C" void kernel_launch(void* const* d_in, const int* in_sizes, int n_in,
                              void* d_out, int out_size) {
    const float* x    = (const float*)d_in[0];
    const int*   ei   = (const int*)d_in[1];     // int32
    const float* ea   = (const float*)d_in[2];
    const float* fc1w = (const float*)d_in[3];
    const float* fc1b = (const float*)d_in[4];
    const float* k1w  = (const float*)d_in[5];
    const float* k1b  = (const float*)d_in[6];
    const float* k2w  = (const float*)d_in[7];
    const float* k2b  = (const float*)d_in[8];
    const float* k3w  = (const float*)d_in[9];
    const float* k3b  = (const float*)d_in[10];
    const float* root = (const float*)d_in[11];
    const float* cb   = (const float*)d_in[12];
    const float* fc2w = (const float*)d_in[13];
    const float* fc2b = (const float*)d_in[14];
    float* out = (float*)d_out;

    float *r1, *r2, *Wd, *Bp2, *Bp3, *hA, *hB, *agg, *inv;
    cudaGetSymbolAddress((void**)&r1,  g_r1);
    cudaGetSymbolAddress((void**)&r2,  g_r2);
    cudaGetSymbolAddress((void**)&Wd,  g_W);
    cudaGetSymbolAddress((void**)&Bp2, g_Bp2);
    cudaGetSymbolAddress((void**)&Bp3, g_Bp3);
    cudaGetSymbolAddress((void**)&hA,  g_hA);
    cudaGetSymbolAddress((void**)&hB,  g_hB);
    cudaGetSymbolAddress((void**)&agg, g_agg);
    cudaGetSymbolAddress((void**)&inv, g_inv);

    // weight prep: transpose to [N,K] + tf32 round + K-permute
    k_prepB<<<dim3(KW / 32, KW / 32), dim3(32, 8)>>>(k2w, Bp2, KW);
    k_prepB<<<dim3(N3 / 32, KW / 32), dim3(32, 8)>>>(k3w, Bp3, N3);

    // edge MLP
    k_mlp1<<<NE * 4, 256>>>(ea, k1w, k1b, r1);
    dim3 g2(KW / 128, (NE + 127) / 128);   // x = N-blocks (fast) for L2 A-reuse
    dim3 g3(N3 / 128, (NE + 127) / 128);
    k_gemm<<<g2, 256>>>(r1, Bp2, k2b, r2, NE, KW, KW, 1);
    k_gemm<<<g3, 256>>>(r2, Bp3, k3b, Wd, NE, N3, KW, 0);

    // degrees
    cudaMemsetAsync(inv, 0, NN * sizeof(float));
    k_deg<<<(NE + 255) / 256, 256>>>(ei, inv);
    k_inv<<<(NN + 255) / 256, 256>>>(inv);

    // initial features
    k_h0<<<(NN * 64) / 256, 256>>>(x, fc1w, fc1b, hA);

    float* hc = hA;
    float* hn = hB;
    for (int d = 0; d < 6; d++) {
        cudaMemsetAsync(agg, 0, (size_t)NN * 64 * sizeof(float));
        k_edge<<<NE / 8, 256>>>(hc, Wd, ei, agg);
        k_update<<<NN / 4, 256>>>(hc, agg, inv, root, cb, hn, d < 5 ? 1 : 0);
        float* tmp = hc; hc = hn; hn = tmp;
    }

    k_final<<<NN / 8, 256>>>(hc, fc2w, fc2b, out);
}

// round 11
// speedup vs baseline: 2.5121x; 1.6356x over previous
#include <cuda_runtime.h>
#include <cuda_bf16.h>
#include <cstdint>

#define NE 100000
#define NN 10000
#define KW 1024
#define N3 4096

// ---- static device scratch (no allocations allowed) ----
__device__ __align__(16) __nv_bfloat16 g_r1[(size_t)NE * KW];  // relu1 [E,1024] bf16 K32-permuted
__device__ __align__(16) __nv_bfloat16 g_r2[(size_t)NE * KW];  // relu2 [E,1024] bf16 K32-permuted
__device__ float g_W[(size_t)NE * N3];                          // W_edge [E,64,64] fp32
__device__ __align__(16) __nv_bfloat16 g_Bp2[(size_t)KW * KW]; // k2_w^T [N,K] bf16 K32-permuted
__device__ __align__(16) __nv_bfloat16 g_Bp3[(size_t)N3 * KW]; // k3_w^T [N,K] bf16 K32-permuted
__device__ float g_hA[NN * 64];
__device__ float g_hB[NN * 64];
__device__ float g_agg[NN * 64];
__device__ float g_inv[NN];

// K-permutation within each 32-group for m16n8k16 fragments:
// pair p=k>>1, group q=(k>>4)&1, hi=(k>>3)&1, t=(k>>1)&3
// 4-byte unit = 4t + 2q + hi  ->  thread t reads 16 contiguous bytes covering
// both k-steps of a BK=32 block: {q0 pair t, q0 pair t+4, q1 pair t, q1 pair t+4}
__device__ __forceinline__ int permk32(int k) {
    return (k & ~31) | (((k >> 1) & 3) << 3) | (((k >> 4) & 1) << 2)
         | (((k >> 3) & 1) << 1) | (k & 1);
}

__device__ __forceinline__ void mma_bf16(float* d, const uint32_t* a, const uint32_t* b) {
    asm volatile(
        "mma.sync.aligned.m16n8k16.row.col.f32.bf16.bf16.f32 "
        "{%0,%1,%2,%3}, {%4,%5,%6,%7}, {%8,%9}, {%0,%1,%2,%3};\n"
        : "+f"(d[0]), "+f"(d[1]), "+f"(d[2]), "+f"(d[3])
        : "r"(a[0]), "r"(a[1]), "r"(a[2]), "r"(a[3]), "r"(b[0]), "r"(b[1]));
}

// ---- B prep: transpose [K,N] -> [N,K], bf16 round, K32-permute ----
__global__ void k_prepB(const float* __restrict__ in, __nv_bfloat16* __restrict__ out, int N) {
    __shared__ float tile[32][33];
    int nb = blockIdx.x * 32, kb = blockIdx.y * 32;
    for (int i = threadIdx.y; i < 32; i += 8)
        tile[i][threadIdx.x] = in[(size_t)(kb + i) * N + nb + threadIdx.x];
    __syncthreads();
    for (int i = threadIdx.y; i < 32; i += 8) {
        int n = nb + i, k = kb + threadIdx.x;
        out[(size_t)n * KW + permk32(k)] = __float2bfloat16(tile[threadIdx.x][i]);
    }
}

// ---- layer 1 of edge MLP: [E,6] @ [6,1024] + b, relu, bf16, permuted write ----
__global__ void k_mlp1(const float* __restrict__ ea, const float* __restrict__ w,
                       const float* __restrict__ b, __nv_bfloat16* __restrict__ out) {
    int idx = blockIdx.x * 256 + threadIdx.x;   // grid exactly E*1024/256
    int e = idx >> 10, n = idx & 1023;
    const float* a = ea + e * 6;
    float s = b[n];
#pragma unroll
    for (int j = 0; j < 6; j++) s = fmaf(a[j], w[j * KW + n], s);
    out[(size_t)e * KW + permk32(n)] = __float2bfloat16(fmaxf(s, 0.f));
}

// ---- bf16 tensor-core GEMM: C[M,N] = A[M,K] @ Bt[N,K]^T + bias ----
// A,B bf16 K32-permuted. BM=BN=128, BK=32, 3-stage cp.async, 8 warps (4M x 2N).
// mode 1: relu -> bf16, permuted write (feeds next GEMM). mode 0: fp32 + bias.
__global__ __launch_bounds__(256, 2)
void k_gemm(const __nv_bfloat16* __restrict__ A, const __nv_bfloat16* __restrict__ B,
            const float* __restrict__ bias, void* __restrict__ Cout,
            int M, int N, int K, int mode) {
    __shared__ __align__(16) __nv_bfloat16 As[3][128][32];   // 3 x 8KB
    __shared__ __align__(16) __nv_bfloat16 Bs[3][128][32];   // 3 x 8KB (48KB total)

    const int tid = threadIdx.x;
    const int warp = tid >> 5, lane = tid & 31;
    const int wm = warp & 3, wn = warp >> 2;
    const int g = lane >> 2, t = lane & 3;
    const int bN = blockIdx.x, bM = blockIdx.y;

    const __nv_bfloat16* Ablk = A + (size_t)bM * 128 * K;
    const __nv_bfloat16* Bblk = B + (size_t)bN * 128 * K;

    float acc[2][8][4];
#pragma unroll
    for (int i = 0; i < 2; i++)
#pragma unroll
        for (int j = 0; j < 8; j++)
#pragma unroll
            for (int q = 0; q < 4; q++) acc[i][j][q] = 0.f;

    auto loadTiles = [&](int kb, int buf) {
        int k0 = kb * 32;
#pragma unroll
        for (int i = 0; i < 2; i++) {   // A: 128 rows x 4 x 16B chunks
            int c = tid + i * 256;
            int row = c >> 2, j = c & 3;
            const __nv_bfloat16* src = Ablk + (size_t)row * K + k0 + j * 8;
            int pr = (bM * 128 + row < M) ? 16 : 0;
            uint32_t da = (uint32_t)__cvta_generic_to_shared(&As[buf][row][j * 8]);
            asm volatile("cp.async.ca.shared.global [%0], [%1], 16, %2;\n"
                         :: "r"(da), "l"(src), "r"(pr));
        }
#pragma unroll
        for (int i = 0; i < 2; i++) {   // B: 128 rows x 4 x 16B chunks
            int c = tid + i * 256;
            int row = c >> 2, j = c & 3;
            const __nv_bfloat16* src = Bblk + (size_t)row * K + k0 + j * 8;
            uint32_t da = (uint32_t)__cvta_generic_to_shared(&Bs[buf][row][j * 8]);
            asm volatile("cp.async.ca.shared.global [%0], [%1], 16;\n"
                         :: "r"(da), "l"(src));
        }
        asm volatile("cp.async.commit_group;\n");
    };

    const int NKB = K / 32;
    loadTiles(0, 0);
    loadTiles(1, 1);
    int buf = 0, nextbuf = 2;
    for (int kb = 0; kb < NKB; kb++) {
        asm volatile("cp.async.wait_group 1;\n");
        __syncthreads();
        if (kb + 2 < NKB) loadTiles(kb + 2, nextbuf);

        uint4 av[2][2];
#pragma unroll
        for (int mt = 0; mt < 2; mt++) {
            int r = wm * 32 + mt * 16;
            av[mt][0] = *(const uint4*)&As[buf][r + g][8 * t];
            av[mt][1] = *(const uint4*)&As[buf][r + g + 8][8 * t];
        }
#pragma unroll
        for (int nt = 0; nt < 8; nt++) {
            int cn = wn * 64 + nt * 8 + g;
            uint4 bv = *(const uint4*)&Bs[buf][cn][8 * t];
            uint32_t b0[2] = { bv.x, bv.y };   // k-step 0
            uint32_t b1[2] = { bv.z, bv.w };   // k-step 1
#pragma unroll
            for (int mt = 0; mt < 2; mt++) {
                uint32_t a0[4] = { av[mt][0].x, av[mt][1].x, av[mt][0].y, av[mt][1].y };
                uint32_t a1[4] = { av[mt][0].z, av[mt][1].z, av[mt][0].w, av[mt][1].w };
                mma_bf16(acc[mt][nt], a0, b0);
                mma_bf16(acc[mt][nt], a1, b1);
            }
        }
        buf = (buf == 2) ? 0 : buf + 1;
        nextbuf = (nextbuf == 2) ? 0 : nextbuf + 1;
    }

    // epilogue
#pragma unroll
    for (int mt = 0; mt < 2; mt++) {
#pragma unroll
        for (int nt = 0; nt < 8; nt++) {
            int col = bN * 128 + wn * 64 + nt * 8 + 2 * t;
            float b0 = bias[col], b1 = bias[col + 1];
            int r0 = bM * 128 + wm * 32 + mt * 16 + g;
            int r1 = r0 + 8;
            float v0 = acc[mt][nt][0] + b0, v1 = acc[mt][nt][1] + b1;
            float v2 = acc[mt][nt][2] + b0, v3 = acc[mt][nt][3] + b1;
            if (mode == 1) {   // relu -> bf16x2, K32-permuted (even/odd cols stay adjacent)
                __nv_bfloat16* Cb = (__nv_bfloat16*)Cout;
                int p0 = permk32(col);
                __nv_bfloat162 h01 = { __float2bfloat16(fmaxf(v0, 0.f)),
                                       __float2bfloat16(fmaxf(v1, 0.f)) };
                __nv_bfloat162 h23 = { __float2bfloat16(fmaxf(v2, 0.f)),
                                       __float2bfloat16(fmaxf(v3, 0.f)) };
                if (r0 < M) *(__nv_bfloat162*)(Cb + (size_t)r0 * N + p0) = h01;
                if (r1 < M) *(__nv_bfloat162*)(Cb + (size_t)r1 * N + p0) = h23;
            } else {
                float* Cf = (float*)Cout;
                if (r0 < M) *(float2*)(Cf + (size_t)r0 * N + col) = make_float2(v0, v1);
                if (r1 < M) *(float2*)(Cf + (size_t)r1 * N + col) = make_float2(v2, v3);
            }
        }
    }
}

// ---- in-degree via atomics (edge_index is int32: JAX downcasts int64) ----
__global__ void k_deg(const int* __restrict__ ei, float* __restrict__ deg) {
    int i = blockIdx.x * 256 + threadIdx.x;
    if (i < NE) atomicAdd(&deg[ei[NE + i]], 1.f);
}
__global__ void k_inv(float* __restrict__ deg) {
    int n = blockIdx.x * 256 + threadIdx.x;
    if (n < NN) { float d = deg[n]; deg[n] = (d > 0.f) ? (1.f / d) : 0.f; }
}

// ---- h0 = x @ fc1_w + fc1_b   (IN_WIDTH = 1) ----
__global__ void k_h0(const float* __restrict__ x, const float* __restrict__ w,
                     const float* __restrict__ b, float* __restrict__ h) {
    int idx = blockIdx.x * 256 + threadIdx.x;   // NN*64 exact
    int n = idx >> 6, o = idx & 63;
    h[idx] = fmaf(x[n], w[o], b[o]);
}

// ---- per-edge matvec + scatter-add: one warp per edge, float2 per lane ----
__global__ __launch_bounds__(256)
void k_edge(const float* __restrict__ h, const float* __restrict__ W,
            const int* __restrict__ ei, float* __restrict__ agg) {
    int warp = threadIdx.x >> 5, lane = threadIdx.x & 31;
    int e = blockIdx.x * 8 + warp;             // NE divisible by 8
    int src = ei[e], dst = ei[NE + e];
    __shared__ float sh[8][64];
    float2 hv = ((const float2*)(h + (size_t)src * 64))[lane];
    sh[warp][2 * lane] = hv.x;
    sh[warp][2 * lane + 1] = hv.y;
    __syncwarp();
    const float2* Wr = (const float2*)(W + (size_t)e * 4096);
    float m0 = 0.f, m1 = 0.f;
#pragma unroll 16
    for (int c = 0; c < 64; c++) {
        float hc = sh[warp][c];
        float2 w = __ldg(&Wr[c * 32 + lane]);
        m0 = fmaf(hc, w.x, m0);
        m1 = fmaf(hc, w.y, m1);
    }
    atomicAdd(&agg[dst * 64 + 2 * lane], m0);
    atomicAdd(&agg[dst * 64 + 2 * lane + 1], m1);
}

// ---- h_new = agg*inv_deg + h@root + conv_b (+relu) ----
__global__ void k_update(const float* __restrict__ hin, const float* __restrict__ agg,
                         const float* __restrict__ inv, const float* __restrict__ root,
                         const float* __restrict__ cb, float* __restrict__ hout, int relu) {
    int ni = threadIdx.x >> 6;
    int node = blockIdx.x * 4 + ni;            // NN divisible by 4
    int o = threadIdx.x & 63;
    __shared__ float sh[4][64];
    sh[ni][o] = hin[node * 64 + o];
    __syncthreads();
    float acc = fmaf(agg[node * 64 + o], inv[node], cb[o]);
#pragma unroll
    for (int c = 0; c < 64; c++) acc = fmaf(sh[ni][c], root[c * 64 + o], acc);
    if (relu) acc = fmaxf(acc, 0.f);
    hout[node * 64 + o] = acc;
}

// ---- out = h @ fc2_w + fc2_b : one warp per node ----
__global__ void k_final(const float* __restrict__ h, const float* __restrict__ w,
                        const float* __restrict__ b, float* __restrict__ out) {
    int node = blockIdx.x * 8 + (threadIdx.x >> 5);  // NN divisible by 8
    int lane = threadIdx.x & 31;
    float v = h[node * 64 + lane] * w[lane] + h[node * 64 + 32 + lane] * w[32 + lane];
#pragma unroll
    for (int s = 16; s > 0; s >>= 1) v += __shfl_xor_sync(0xffffffffu, v, s);
    if (lane == 0) out[node] = v + b[0];
}

extern "C" void kernel_launch(void* const* d_in, const int* in_sizes, int n_in,
                              void* d_out, int out_size) {
    const float* x    = (const float*)d_in[0];
    const int*   ei   = (const int*)d_in[1];     // int32
    const float* ea   = (const float*)d_in[2];
    const float* fc1w = (const float*)d_in[3];
    const float* fc1b = (const float*)d_in[4];
    const float* k1w  = (const float*)d_in[5];
    const float* k1b  = (const float*)d_in[6];
    const float* k2w  = (const float*)d_in[7];
    const float* k2b  = (const float*)d_in[8];
    const float* k3w  = (const float*)d_in[9];
    const float* k3b  = (const float*)d_in[10];
    const float* root = (const float*)d_in[11];
    const float* cb   = (const float*)d_in[12];
    const float* fc2w = (const float*)d_in[13];
    const float* fc2b = (const float*)d_in[14];
    float* out = (float*)d_out;

    __nv_bfloat16 *r1, *r2, *Bp2, *Bp3;
    float *Wd, *hA, *hB, *agg, *inv;
    cudaGetSymbolAddress((void**)&r1,  g_r1);
    cudaGetSymbolAddress((void**)&r2,  g_r2);
    cudaGetSymbolAddress((void**)&Wd,  g_W);
    cudaGetSymbolAddress((void**)&Bp2, g_Bp2);
    cudaGetSymbolAddress((void**)&Bp3, g_Bp3);
    cudaGetSymbolAddress((void**)&hA,  g_hA);
    cudaGetSymbolAddress((void**)&hB,  g_hB);
    cudaGetSymbolAddress((void**)&agg, g_agg);
    cudaGetSymbolAddress((void**)&inv, g_inv);

    // weight prep: transpose to [N,K] + bf16 round + K32-permute
    k_prepB<<<dim3(KW / 32, KW / 32), dim3(32, 8)>>>(k2w, Bp2, KW);
    k_prepB<<<dim3(N3 / 32, KW / 32), dim3(32, 8)>>>(k3w, Bp3, N3);

    // edge MLP
    k_mlp1<<<NE * 4, 256>>>(ea, k1w, k1b, r1);
    dim3 g2(KW / 128, (NE + 127) / 128);   // x = N-blocks (fast) for L2 A-reuse
    dim3 g3(N3 / 128, (NE + 127) / 128);
    k_gemm<<<g2, 256>>>(r1, Bp2, k2b, r2, NE, KW, KW, 1);
    k_gemm<<<g3, 256>>>(r2, Bp3, k3b, Wd, NE, N3, KW, 0);

    // degrees
    cudaMemsetAsync(inv, 0, NN * sizeof(float));
    k_deg<<<(NE + 255) / 256, 256>>>(ei, inv);
    k_inv<<<(NN + 255) / 256, 256>>>(inv);

    // initial features
    k_h0<<<(NN * 64) / 256, 256>>>(x, fc1w, fc1b, hA);

    float* hc = hA;
    float* hn = hB;
    for (int d = 0; d < 6; d++) {
        cudaMemsetAsync(agg, 0, (size_t)NN * 64 * sizeof(float));
        k_edge<<<NE / 8, 256>>>(hc, Wd, ei, agg);
        k_update<<<NN / 4, 256>>>(hc, agg, inv, root, cb, hn, d < 5 ? 1 : 0);
        float* tmp = hc; hc = hn; hn = tmp;
    }

    k_final<<<NN / 8, 256>>>(hc, fc2w, fc2b, out);
}

// round 13
// speedup vs baseline: 2.8819x; 1.1472x over previous
#include <cuda_runtime.h>
#include <cuda_bf16.h>
#include <cstdint>

#define NE 100000
#define NN 10000
#define KW 1024
#define N3 4096

// ---- static device scratch (no allocations allowed) ----
__device__ __align__(16) __nv_bfloat16 g_r1[(size_t)NE * KW];   // relu1 [E,1024] bf16 K32-permuted
__device__ __align__(16) __nv_bfloat16 g_r2[(size_t)NE * KW];   // relu2 [E,1024] bf16 K32-permuted
__device__ __align__(16) __nv_bfloat16 g_W[(size_t)NE * N3];    // W_edge [E,64,64] bf16 normal
__device__ __align__(16) __nv_bfloat16 g_Bp2[(size_t)KW * KW];  // k2_w^T [N,K] bf16 K32-permuted
__device__ __align__(16) __nv_bfloat16 g_Bp3[(size_t)N3 * KW];  // k3_w^T [N,K] bf16 K32-permuted
__device__ float g_hA[NN * 64];
__device__ float g_hB[NN * 64];
__device__ float g_agg[NN * 64];
__device__ float g_inv[NN];

// K-permutation within each 32-group for m16n8k16 fragments (proven R11 layout):
// 4-byte unit = 4t + 2q + hi  ->  thread t reads 16 contiguous bytes covering
// both k-steps of a BK=32 sub-block.
__device__ __forceinline__ int permk32(int k) {
    return (k & ~31) | (((k >> 1) & 3) << 3) | (((k >> 4) & 1) << 2)
         | (((k >> 3) & 1) << 1) | (k & 1);
}

__device__ __forceinline__ void mma_bf16(float* d, const uint32_t* a, const uint32_t* b) {
    asm volatile(
        "mma.sync.aligned.m16n8k16.row.col.f32.bf16.bf16.f32 "
        "{%0,%1,%2,%3}, {%4,%5,%6,%7}, {%8,%9}, {%0,%1,%2,%3};\n"
        : "+f"(d[0]), "+f"(d[1]), "+f"(d[2]), "+f"(d[3])
        : "r"(a[0]), "r"(a[1]), "r"(a[2]), "r"(a[3]), "r"(b[0]), "r"(b[1]));
}

// ---- B prep: transpose [K,N] -> [N,K], bf16 round, K32-permute ----
__global__ void k_prepB(const float* __restrict__ in, __nv_bfloat16* __restrict__ out, int N) {
    __shared__ float tile[32][33];
    int nb = blockIdx.x * 32, kb = blockIdx.y * 32;
    for (int i = threadIdx.y; i < 32; i += 8)
        tile[i][threadIdx.x] = in[(size_t)(kb + i) * N + nb + threadIdx.x];
    __syncthreads();
    for (int i = threadIdx.y; i < 32; i += 8) {
        int n = nb + i, k = kb + threadIdx.x;
        out[(size_t)n * KW + permk32(k)] = __float2bfloat16(tile[threadIdx.x][i]);
    }
}

// ---- layer 1 of edge MLP: [E,6] @ [6,1024] + b, relu, bf16, permuted write ----
__global__ void k_mlp1(const float* __restrict__ ea, const float* __restrict__ w,
                       const float* __restrict__ b, __nv_bfloat16* __restrict__ out) {
    int idx = blockIdx.x * 256 + threadIdx.x;
    int e = idx >> 10, n = idx & 1023;
    const float* a = ea + e * 6;
    float s = b[n];
#pragma unroll
    for (int j = 0; j < 6; j++) s = fmaf(a[j], w[j * KW + n], s);
    out[(size_t)e * KW + permk32(n)] = __float2bfloat16(fmaxf(s, 0.f));
}

// ---- bf16 mma.sync GEMM: C[M,N] = A[M,K] @ Bt[N,K]^T + bias ----
// BM=BN=128. Pipeline step = BK=64 (two BK=32 sub-tiles, 64B-pitch conflict-free).
// 3 stages x 32KB dynamic smem, ONE __syncthreads per step.
// mode 1: relu -> bf16 K32-permuted (feeds next GEMM). mode 0: bf16 normal + bias.
#define STG_BYTES 32768   // A0(8K) A1(8K) B0(8K) B1(8K)
#define SM_BYTES  (3 * STG_BYTES)

__global__ __launch_bounds__(256, 2)
void k_gemm(const __nv_bfloat16* __restrict__ A, const __nv_bfloat16* __restrict__ B,
            const float* __restrict__ bias, __nv_bfloat16* __restrict__ C,
            int M, int N, int K, int mode) {
    extern __shared__ __align__(16) char smem[];

    const int tid = threadIdx.x;
    const int warp = tid >> 5, lane = tid & 31;
    const int wm = warp & 3, wn = warp >> 2;
    const int g = lane >> 2, t = lane & 3;
    const int bN = blockIdx.x, bM = blockIdx.y;

    const __nv_bfloat16* Ablk = A + (size_t)bM * 128 * K;
    const __nv_bfloat16* Bblk = B + (size_t)bN * 128 * K;

    float acc[2][8][4];
#pragma unroll
    for (int i = 0; i < 2; i++)
#pragma unroll
        for (int j = 0; j < 8; j++)
#pragma unroll
            for (int q = 0; q < 4; q++) acc[i][j][q] = 0.f;

    // load one BK=64 chunk (= 2 x BK=32 sub-tiles) into stage s
    auto loadChunk = [&](int c, int s) {
        char* stg = smem + s * STG_BYTES;
#pragma unroll
        for (int i = 0; i < 4; i++) {   // A: 2 subs x 128 rows x 4 x 16B = 1024 chunks
            int idx = tid + i * 256;
            int sub = idx >> 9, rem = idx & 511;
            int row = rem >> 2, j = rem & 3;
            const __nv_bfloat16* src = Ablk + (size_t)row * K + c * 64 + sub * 32 + j * 8;
            int pr = (bM * 128 + row < M) ? 16 : 0;
            uint32_t da = (uint32_t)__cvta_generic_to_shared(stg + sub * 8192 + row * 64 + j * 16);
            asm volatile("cp.async.ca.shared.global [%0], [%1], 16, %2;\n"
                         :: "r"(da), "l"(src), "r"(pr));
        }
#pragma unroll
        for (int i = 0; i < 4; i++) {   // B: same geometry at +16KB
            int idx = tid + i * 256;
            int sub = idx >> 9, rem = idx & 511;
            int row = rem >> 2, j = rem & 3;
            const __nv_bfloat16* src = Bblk + (size_t)row * K + c * 64 + sub * 32 + j * 8;
            uint32_t da = (uint32_t)__cvta_generic_to_shared(stg + 16384 + sub * 8192 + row * 64 + j * 16);
            asm volatile("cp.async.ca.shared.global [%0], [%1], 16;\n"
                         :: "r"(da), "l"(src));
        }
        asm volatile("cp.async.commit_group;\n");
    };

    const int NCH = K / 64;            // 16
    loadChunk(0, 0);
    loadChunk(1, 1);
    int s = 0, ld = 2;                 // stage of chunk c; stage for chunk c+2
    for (int c = 0; c < NCH; c++) {
        if (c + 1 < NCH) asm volatile("cp.async.wait_group 1;" ::: "memory");
        else             asm volatile("cp.async.wait_group 0;" ::: "memory");
        __syncthreads();               // all warps done with stage 'ld' (computed at c-1)
        if (c + 2 < NCH) loadChunk(c + 2, ld);

        const char* stg = smem + s * STG_BYTES;
#pragma unroll
        for (int u = 0; u < 2; u++) {  // two BK=32 sub-tiles
            const char* As = stg + u * 8192;
            const char* Bs = stg + 16384 + u * 8192;
            uint4 av[2][2];
#pragma unroll
            for (int mt = 0; mt < 2; mt++) {
                int r = wm * 32 + mt * 16;
                av[mt][0] = *(const uint4*)(As + (r + g) * 64 + 16 * t);
                av[mt][1] = *(const uint4*)(As + (r + g + 8) * 64 + 16 * t);
            }
#pragma unroll
            for (int nt = 0; nt < 8; nt++) {
                int cn = wn * 64 + nt * 8 + g;
                uint4 bv = *(const uint4*)(Bs + cn * 64 + 16 * t);
                uint32_t b0[2] = { bv.x, bv.y };
                uint32_t b1[2] = { bv.z, bv.w };
#pragma unroll
                for (int mt = 0; mt < 2; mt++) {
                    uint32_t a0[4] = { av[mt][0].x, av[mt][1].x, av[mt][0].y, av[mt][1].y };
                    uint32_t a1[4] = { av[mt][0].z, av[mt][1].z, av[mt][0].w, av[mt][1].w };
                    mma_bf16(acc[mt][nt], a0, b0);
                    mma_bf16(acc[mt][nt], a1, b1);
                }
            }
        }
        s = (s == 2) ? 0 : s + 1;
        ld = (ld == 2) ? 0 : ld + 1;
    }

    // epilogue: bf16 stores always
#pragma unroll
    for (int mt = 0; mt < 2; mt++) {
#pragma unroll
        for (int nt = 0; nt < 8; nt++) {
            int col = bN * 128 + wn * 64 + nt * 8 + 2 * t;
            float b0 = bias[col], b1 = bias[col + 1];
            int r0 = bM * 128 + wm * 32 + mt * 16 + g;
            int r1 = r0 + 8;
            float v0 = acc[mt][nt][0] + b0, v1 = acc[mt][nt][1] + b1;
            float v2 = acc[mt][nt][2] + b0, v3 = acc[mt][nt][3] + b1;
            int oc;
            if (mode == 1) {           // relu + permuted (even/odd pair stays adjacent)
                v0 = fmaxf(v0, 0.f); v1 = fmaxf(v1, 0.f);
                v2 = fmaxf(v2, 0.f); v3 = fmaxf(v3, 0.f);
                oc = permk32(col);
            } else {
                oc = col;
            }
            __nv_bfloat162 h01 = { __float2bfloat16(v0), __float2bfloat16(v1) };
            __nv_bfloat162 h23 = { __float2bfloat16(v2), __float2bfloat16(v3) };
            if (r0 < M) *(__nv_bfloat162*)(C + (size_t)r0 * N + oc) = h01;
            if (r1 < M) *(__nv_bfloat162*)(C + (size_t)r1 * N + oc) = h23;
        }
    }
}

// ---- in-degree via atomics (edge_index is int32: JAX downcasts int64) ----
__global__ void k_deg(const int* __restrict__ ei, float* __restrict__ deg) {
    int i = blockIdx.x * 256 + threadIdx.x;
    if (i < NE) atomicAdd(&deg[ei[NE + i]], 1.f);
}
__global__ void k_inv(float* __restrict__ deg) {
    int n = blockIdx.x * 256 + threadIdx.x;
    if (n < NN) { float d = deg[n]; deg[n] = (d > 0.f) ? (1.f / d) : 0.f; }
}

// ---- h0 = x @ fc1_w + fc1_b (IN_WIDTH = 1) ----
__global__ void k_h0(const float* __restrict__ x, const float* __restrict__ w,
                     const float* __restrict__ b, float* __restrict__ h) {
    int idx = blockIdx.x * 256 + threadIdx.x;
    int n = idx >> 6, o = idx & 63;
    h[idx] = fmaf(x[n], w[o], b[o]);
}

// ---- per-edge matvec + scatter-add: one warp per edge, bf16x2 W ----
__global__ __launch_bounds__(256)
void k_edge(const float* __restrict__ h, const __nv_bfloat16* __restrict__ W,
            const int* __restrict__ ei, float* __restrict__ agg) {
    int warp = threadIdx.x >> 5, lane = threadIdx.x & 31;
    int e = blockIdx.x * 8 + warp;             // NE divisible by 8
    int src = ei[e], dst = ei[NE + e];
    __shared__ float sh[8][64];
    float2 hv = ((const float2*)(h + (size_t)src * 64))[lane];
    sh[warp][2 * lane] = hv.x;
    sh[warp][2 * lane + 1] = hv.y;
    __syncwarp();
    const uint32_t* Wr = (const uint32_t*)(W + (size_t)e * 4096);
    float m0 = 0.f, m1 = 0.f;
#pragma unroll 16
    for (int c = 0; c < 64; c++) {
        float hc = sh[warp][c];
        uint32_t wv = __ldg(&Wr[c * 32 + lane]);
        float2 wf = __bfloat1622float2(*(__nv_bfloat162*)&wv);
        m0 = fmaf(hc, wf.x, m0);
        m1 = fmaf(hc, wf.y, m1);
    }
    atomicAdd(&agg[dst * 64 + 2 * lane], m0);
    atomicAdd(&agg[dst * 64 + 2 * lane + 1], m1);
}

// ---- h_new = agg*inv_deg + h@root + conv_b (+relu) ----
__global__ void k_update(const float* __restrict__ hin, const float* __restrict__ agg,
                         const float* __restrict__ inv, const float* __restrict__ root,
                         const float* __restrict__ cb, float* __restrict__ hout, int relu) {
    int ni = threadIdx.x >> 6;
    int node = blockIdx.x * 4 + ni;
    int o = threadIdx.x & 63;
    __shared__ float sh[4][64];
    sh[ni][o] = hin[node * 64 + o];
    __syncthreads();
    float acc = fmaf(agg[node * 64 + o], inv[node], cb[o]);
#pragma unroll
    for (int c = 0; c < 64; c++) acc = fmaf(sh[ni][c], root[c * 64 + o], acc);
    if (relu) acc = fmaxf(acc, 0.f);
    hout[node * 64 + o] = acc;
}

// ---- out = h @ fc2_w + fc2_b : one warp per node ----
__global__ void k_final(const float* __restrict__ h, const float* __restrict__ w,
                        const float* __restrict__ b, float* __restrict__ out) {
    int node = blockIdx.x * 8 + (threadIdx.x >> 5);
    int lane = threadIdx.x & 31;
    float v = h[node * 64 + lane] * w[lane] + h[node * 64 + 32 + lane] * w[32 + lane];
#pragma unroll
    for (int s = 16; s > 0; s >>= 1) v += __shfl_xor_sync(0xffffffffu, v, s);
    if (lane == 0) out[node] = v + b[0];
}

extern "C" void kernel_launch(void* const* d_in, const int* in_sizes, int n_in,
                              void* d_out, int out_size) {
    const float* x    = (const float*)d_in[0];
    const int*   ei   = (const int*)d_in[1];     // int32
    const float* ea   = (const float*)d_in[2];
    const float* fc1w = (const float*)d_in[3];
    const float* fc1b = (const float*)d_in[4];
    const float* k1w  = (const float*)d_in[5];
    const float* k1b  = (const float*)d_in[6];
    const float* k2w  = (const float*)d_in[7];
    const float* k2b  = (const float*)d_in[8];
    const float* k3w  = (const float*)d_in[9];
    const float* k3b  = (const float*)d_in[10];
    const float* root = (const float*)d_in[11];
    const float* cb   = (const float*)d_in[12];
    const float* fc2w = (const float*)d_in[13];
    const float* fc2b = (const float*)d_in[14];
    float* out = (float*)d_out;

    __nv_bfloat16 *r1, *r2, *Wd, *Bp2, *Bp3;
    float *hA, *hB, *agg, *inv;
    cudaGetSymbolAddress((void**)&r1,  g_r1);
    cudaGetSymbolAddress((void**)&r2,  g_r2);
    cudaGetSymbolAddress((void**)&Wd,  g_W);
    cudaGetSymbolAddress((void**)&Bp2, g_Bp2);
    cudaGetSymbolAddress((void**)&Bp3, g_Bp3);
    cudaGetSymbolAddress((void**)&hA,  g_hA);
    cudaGetSymbolAddress((void**)&hB,  g_hB);
    cudaGetSymbolAddress((void**)&agg, g_agg);
    cudaGetSymbolAddress((void**)&inv, g_inv);

    cudaFuncSetAttribute(k_gemm, cudaFuncAttributeMaxDynamicSharedMemorySize, SM_BYTES);

    // weight prep: transpose to [N,K] + bf16 round + K32-permute
    k_prepB<<<dim3(KW / 32, KW / 32), dim3(32, 8)>>>(k2w, Bp2, KW);
    k_prepB<<<dim3(N3 / 32, KW / 32), dim3(32, 8)>>>(k3w, Bp3, N3);

    // edge MLP
    k_mlp1<<<NE * 4, 256>>>(ea, k1w, k1b, r1);
    dim3 g2(KW / 128, (NE + 127) / 128);   // x = N-blocks (fast) for L2 A-reuse
    dim3 g3(N3 / 128, (NE + 127) / 128);
    k_gemm<<<g2, 256, SM_BYTES>>>(r1, Bp2, k2b, r2, NE, KW, KW, 1);
    k_gemm<<<g3, 256, SM_BYTES>>>(r2, Bp3, k3b, Wd, NE, N3, KW, 0);

    // degrees
    cudaMemsetAsync(inv, 0, NN * sizeof(float));
    k_deg<<<(NE + 255) / 256, 256>>>(ei, inv);
    k_inv<<<(NN + 255) / 256, 256>>>(inv);

    // initial features
    k_h0<<<(NN * 64) / 256, 256>>>(x, fc1w, fc1b, hA);

    float* hc = hA;
    float* hn = hB;
    for (int d = 0; d < 6; d++) {
        cudaMemsetAsync(agg, 0, (size_t)NN * 64 * sizeof(float));
        k_edge<<<NE / 8, 256>>>(hc, Wd, ei, agg);
        k_update<<<NN / 4, 256>>>(hc, agg, inv, root, cb, hn, d < 5 ? 1 : 0);
        float* tmp = hc; hc = hn; hn = tmp;
    }

    k_final<<<NN / 8, 256>>>(hc, fc2w, fc2b, out);
}

// round 14
// speedup vs baseline: 3.0144x; 1.0460x over previous
#include <cuda_runtime.h>
#include <cuda_bf16.h>
#include <cstdint>

#define NE 100000
#define NN 10000
#define KW 1024
#define N3 4096

// ---- static device scratch (no allocations allowed) ----
__device__ __align__(16) __nv_bfloat16 g_r1[(size_t)NE * KW];   // relu1 [E,1024] bf16 K32-permuted
__device__ __align__(16) __nv_bfloat16 g_r2[(size_t)NE * KW];   // relu2 [E,1024] bf16 K32-permuted
__device__ __align__(16) __nv_bfloat16 g_W[(size_t)NE * N3];    // W_edge [E,64,64] bf16 normal
__device__ __align__(16) __nv_bfloat16 g_Bp2[(size_t)KW * KW];  // k2_w^T [N,K] bf16 K32-permuted
__device__ __align__(16) __nv_bfloat16 g_Bp3[(size_t)N3 * KW];  // k3_w^T [N,K] bf16 K32-permuted
__device__ float g_hA[NN * 64];
__device__ float g_hB[NN * 64];
__device__ float g_agg[NN * 64];
__device__ float g_inv[NN];

// K-permutation within each 32-group for m16n8k16 fragments (proven layout):
// 4-byte unit = 4t + 2q + hi -> thread t reads 16 contiguous bytes covering
// both k-steps of a BK=32 sub-block.
__device__ __forceinline__ int permk32(int k) {
    return (k & ~31) | (((k >> 1) & 3) << 3) | (((k >> 4) & 1) << 2)
         | (((k >> 3) & 1) << 1) | (k & 1);
}

__device__ __forceinline__ void mma_bf16(float* d, const uint32_t* a, const uint32_t* b) {
    asm volatile(
        "mma.sync.aligned.m16n8k16.row.col.f32.bf16.bf16.f32 "
        "{%0,%1,%2,%3}, {%4,%5,%6,%7}, {%8,%9}, {%0,%1,%2,%3};\n"
        : "+f"(d[0]), "+f"(d[1]), "+f"(d[2]), "+f"(d[3])
        : "r"(a[0]), "r"(a[1]), "r"(a[2]), "r"(a[3]), "r"(b[0]), "r"(b[1]));
}

// ---- B prep: transpose [K,N] -> [N,K], bf16 round, K32-permute ----
__global__ void k_prepB(const float* __restrict__ in, __nv_bfloat16* __restrict__ out, int N) {
    __shared__ float tile[32][33];
    int nb = blockIdx.x * 32, kb = blockIdx.y * 32;
    for (int i = threadIdx.y; i < 32; i += 8)
        tile[i][threadIdx.x] = in[(size_t)(kb + i) * N + nb + threadIdx.x];
    __syncthreads();
    for (int i = threadIdx.y; i < 32; i += 8) {
        int n = nb + i, k = kb + threadIdx.x;
        out[(size_t)n * KW + permk32(k)] = __float2bfloat16(tile[threadIdx.x][i]);
    }
}

// ---- layer 1 of edge MLP: [E,6] @ [6,1024] + b, relu, bf16, permuted write ----
__global__ void k_mlp1(const float* __restrict__ ea, const float* __restrict__ w,
                       const float* __restrict__ b, __nv_bfloat16* __restrict__ out) {
    int idx = blockIdx.x * 256 + threadIdx.x;
    int e = idx >> 10, n = idx & 1023;
    const float* a = ea + e * 6;
    float s = b[n];
#pragma unroll
    for (int j = 0; j < 6; j++) s = fmaf(a[j], w[j * KW + n], s);
    out[(size_t)e * KW + permk32(n)] = __float2bfloat16(fmaxf(s, 0.f));
}

// ---- bf16 mma.sync GEMM: C[M,N] = A[M,K] @ Bt[N,K]^T + bias ----
// CTA tile 128x256, 8 warps (2M x 4N) of 64x64 warp tiles. BK=64 steps
// (2 x BK=32 sub-tiles, 64B-pitch conflict-free rows). 3 stages x 48KB smem,
// 1 CTA/SM. mode 1: relu -> bf16 K32-permuted. mode 0: bf16 normal.
#define STG_BYTES 49152   // A: 2x8KB, B: 2x16KB
#define SM_BYTES  (3 * STG_BYTES)

__global__ __launch_bounds__(256, 1)
void k_gemm(const __nv_bfloat16* __restrict__ A, const __nv_bfloat16* __restrict__ B,
            const float* __restrict__ bias, __nv_bfloat16* __restrict__ C,
            int M, int N, int K, int mode) {
    extern __shared__ __align__(16) char smem[];

    const int tid = threadIdx.x;
    const int warp = tid >> 5, lane = tid & 31;
    const int wm = warp & 1, wn = warp >> 1;      // 2M x 4N warps
    const int g = lane >> 2, t = lane & 3;
    const int bN = blockIdx.x, bM = blockIdx.y;

    const __nv_bfloat16* Ablk = A + (size_t)bM * 128 * K;
    const __nv_bfloat16* Bblk = B + (size_t)bN * 256 * K;

    float acc[4][8][4];
#pragma unroll
    for (int i = 0; i < 4; i++)
#pragma unroll
        for (int j = 0; j < 8; j++)
#pragma unroll
            for (int q = 0; q < 4; q++) acc[i][j][q] = 0.f;

    // load one BK=64 chunk (2 x BK=32 sub-tiles) into stage s
    auto loadChunk = [&](int c, int s) {
        char* stg = smem + s * STG_BYTES;
#pragma unroll
        for (int i = 0; i < 4; i++) {   // A: 2 subs x 128 rows x 4 x 16B = 1024
            int idx = tid + i * 256;
            int sub = idx >> 9, rem = idx & 511;
            int row = rem >> 2, j = rem & 3;
            const __nv_bfloat16* src = Ablk + (size_t)row * K + c * 64 + sub * 32 + j * 8;
            int pr = (bM * 128 + row < M) ? 16 : 0;
            uint32_t da = (uint32_t)__cvta_generic_to_shared(stg + sub * 8192 + row * 64 + j * 16);
            asm volatile("cp.async.cg.shared.global [%0], [%1], 16, %2;\n"
                         :: "r"(da), "l"(src), "r"(pr));
        }
#pragma unroll
        for (int i = 0; i < 8; i++) {   // B: 2 subs x 256 rows x 4 x 16B = 2048
            int idx = tid + i * 256;
            int sub = idx >> 10, rem = idx & 1023;
            int row = rem >> 2, j = rem & 3;
            const __nv_bfloat16* src = Bblk + (size_t)row * K + c * 64 + sub * 32 + j * 8;
            uint32_t da = (uint32_t)__cvta_generic_to_shared(stg + 16384 + sub * 16384 + row * 64 + j * 16);
            asm volatile("cp.async.cg.shared.global [%0], [%1], 16;\n"
                         :: "r"(da), "l"(src));
        }
        asm volatile("cp.async.commit_group;\n");
    };

    const int NCH = K / 64;            // 16
    loadChunk(0, 0);
    loadChunk(1, 1);
    int s = 0, ld = 2;
    for (int c = 0; c < NCH; c++) {
        if (c + 1 < NCH) asm volatile("cp.async.wait_group 1;" ::: "memory");
        else             asm volatile("cp.async.wait_group 0;" ::: "memory");
        __syncthreads();
        if (c + 2 < NCH) loadChunk(c + 2, ld);

        const char* stg = smem + s * STG_BYTES;
#pragma unroll
        for (int u = 0; u < 2; u++) {  // two BK=32 sub-tiles
            const char* As = stg + u * 8192;
            const char* Bs = stg + 16384 + u * 16384;
            uint4 av[4][2];
#pragma unroll
            for (int mt = 0; mt < 4; mt++) {
                int r = wm * 64 + mt * 16;
                av[mt][0] = *(const uint4*)(As + (r + g) * 64 + 16 * t);
                av[mt][1] = *(const uint4*)(As + (r + g + 8) * 64 + 16 * t);
            }
#pragma unroll
            for (int nt = 0; nt < 8; nt++) {
                int cn = wn * 64 + nt * 8 + g;
                uint4 bv = *(const uint4*)(Bs + cn * 64 + 16 * t);
                uint32_t b0[2] = { bv.x, bv.y };
                uint32_t b1[2] = { bv.z, bv.w };
#pragma unroll
                for (int mt = 0; mt < 4; mt++) {
                    uint32_t a0[4] = { av[mt][0].x, av[mt][1].x, av[mt][0].y, av[mt][1].y };
                    uint32_t a1[4] = { av[mt][0].z, av[mt][1].z, av[mt][0].w, av[mt][1].w };
                    mma_bf16(acc[mt][nt], a0, b0);
                    mma_bf16(acc[mt][nt], a1, b1);
                }
            }
        }
        s = (s == 2) ? 0 : s + 1;
        ld = (ld == 2) ? 0 : ld + 1;
    }

    // epilogue: bf16 stores always
#pragma unroll
    for (int mt = 0; mt < 4; mt++) {
#pragma unroll
        for (int nt = 0; nt < 8; nt++) {
            int col = bN * 256 + wn * 64 + nt * 8 + 2 * t;
            float b0 = bias[col], b1 = bias[col + 1];
            int r0 = bM * 128 + wm * 64 + mt * 16 + g;
            int r1 = r0 + 8;
            float v0 = acc[mt][nt][0] + b0, v1 = acc[mt][nt][1] + b1;
            float v2 = acc[mt][nt][2] + b0, v3 = acc[mt][nt][3] + b1;
            int oc;
            if (mode == 1) {           // relu + permuted (even/odd pair stays adjacent)
                v0 = fmaxf(v0, 0.f); v1 = fmaxf(v1, 0.f);
                v2 = fmaxf(v2, 0.f); v3 = fmaxf(v3, 0.f);
                oc = permk32(col);
            } else {
                oc = col;
            }
            __nv_bfloat162 h01 = { __float2bfloat16(v0), __float2bfloat16(v1) };
            __nv_bfloat162 h23 = { __float2bfloat16(v2), __float2bfloat16(v3) };
            if (r0 < M) *(__nv_bfloat162*)(C + (size_t)r0 * N + oc) = h01;
            if (r1 < M) *(__nv_bfloat162*)(C + (size_t)r1 * N + oc) = h23;
        }
    }
}

// ---- in-degree via atomics (edge_index is int32: JAX downcasts int64) ----
__global__ void k_deg(const int* __restrict__ ei, float* __restrict__ deg) {
    int i = blockIdx.x * 256 + threadIdx.x;
    if (i < NE) atomicAdd(&deg[ei[NE + i]], 1.f);
}
__global__ void k_inv(float* __restrict__ deg) {
    int n = blockIdx.x * 256 + threadIdx.x;
    if (n < NN) { float d = deg[n]; deg[n] = (d > 0.f) ? (1.f / d) : 0.f; }
}

// ---- h0 = x @ fc1_w + fc1_b (IN_WIDTH = 1) ----
__global__ void k_h0(const float* __restrict__ x, const float* __restrict__ w,
                     const float* __restrict__ b, float* __restrict__ h) {
    int idx = blockIdx.x * 256 + threadIdx.x;
    int n = idx >> 6, o = idx & 63;
    h[idx] = fmaf(x[n], w[o], b[o]);
}

// ---- per-edge matvec + scatter-add: one warp per edge, bf16x2 W ----
__global__ __launch_bounds__(256)
void k_edge(const float* __restrict__ h, const __nv_bfloat16* __restrict__ W,
            const int* __restrict__ ei, float* __restrict__ agg) {
    int warp = threadIdx.x >> 5, lane = threadIdx.x & 31;
    int e = blockIdx.x * 8 + warp;             // NE divisible by 8
    int src = ei[e], dst = ei[NE + e];
    __shared__ float sh[8][64];
    float2 hv = ((const float2*)(h + (size_t)src * 64))[lane];
    sh[warp][2 * lane] = hv.x;
    sh[warp][2 * lane + 1] = hv.y;
    __syncwarp();
    const uint32_t* Wr = (const uint32_t*)(W + (size_t)e * 4096);
    float m0 = 0.f, m1 = 0.f;
#pragma unroll 16
    for (int c = 0; c < 64; c++) {
        float hc = sh[warp][c];
        uint32_t wv = __ldg(&Wr[c * 32 + lane]);
        float2 wf = __bfloat1622float2(*(__nv_bfloat162*)&wv);
        m0 = fmaf(hc, wf.x, m0);
        m1 = fmaf(hc, wf.y, m1);
    }
    atomicAdd(&agg[dst * 64 + 2 * lane], m0);
    atomicAdd(&agg[dst * 64 + 2 * lane + 1], m1);
}

// ---- h_new = agg*inv_deg + h@root + conv_b (+relu) ----
__global__ void k_update(const float* __restrict__ hin, const float* __restrict__ agg,
                         const float* __restrict__ inv, const float* __restrict__ root,
                         const float* __restrict__ cb, float* __restrict__ hout, int relu) {
    int ni = threadIdx.x >> 6;
    int node = blockIdx.x * 4 + ni;
    int o = threadIdx.x & 63;
    __shared__ float sh[4][64];
    sh[ni][o] = hin[node * 64 + o];
    __syncthreads();
    float acc = fmaf(agg[node * 64 + o], inv[node], cb[o]);
#pragma unroll
    for (int c = 0; c < 64; c++) acc = fmaf(sh[ni][c], root[c * 64 + o], acc);
    if (relu) acc = fmaxf(acc, 0.f);
    hout[node * 64 + o] = acc;
}

// ---- out = h @ fc2_w + fc2_b : one warp per node ----
__global__ void k_final(const float* __restrict__ h, const float* __restrict__ w,
                        const float* __restrict__ b, float* __restrict__ out) {
    int node = blockIdx.x * 8 + (threadIdx.x >> 5);
    int lane = threadIdx.x & 31;
    float v = h[node * 64 + lane] * w[lane] + h[node * 64 + 32 + lane] * w[32 + lane];
#pragma unroll
    for (int s = 16; s > 0; s >>= 1) v += __shfl_xor_sync(0xffffffffu, v, s);
    if (lane == 0) out[node] = v + b[0];
}

extern "C" void kernel_launch(void* const* d_in, const int* in_sizes, int n_in,
                              void* d_out, int out_size) {
    const float* x    = (const float*)d_in[0];
    const int*   ei   = (const int*)d_in[1];     // int32
    const float* ea   = (const float*)d_in[2];
    const float* fc1w = (const float*)d_in[3];
    const float* fc1b = (const float*)d_in[4];
    const float* k1w  = (const float*)d_in[5];
    const float* k1b  = (const float*)d_in[6];
    const float* k2w  = (const float*)d_in[7];
    const float* k2b  = (const float*)d_in[8];
    const float* k3w  = (const float*)d_in[9];
    const float* k3b  = (const float*)d_in[10];
    const float* root = (const float*)d_in[11];
    const float* cb   = (const float*)d_in[12];
    const float* fc2w = (const float*)d_in[13];
    const float* fc2b = (const float*)d_in[14];
    float* out = (float*)d_out;

    __nv_bfloat16 *r1, *r2, *Wd, *Bp2, *Bp3;
    float *hA, *hB, *agg, *inv;
    cudaGetSymbolAddress((void**)&r1,  g_r1);
    cudaGetSymbolAddress((void**)&r2,  g_r2);
    cudaGetSymbolAddress((void**)&Wd,  g_W);
    cudaGetSymbolAddress((void**)&Bp2, g_Bp2);
    cudaGetSymbolAddress((void**)&Bp3, g_Bp3);
    cudaGetSymbolAddress((void**)&hA,  g_hA);
    cudaGetSymbolAddress((void**)&hB,  g_hB);
    cudaGetSymbolAddress((void**)&agg, g_agg);
    cudaGetSymbolAddress((void**)&inv, g_inv);

    cudaFuncSetAttribute(k_gemm, cudaFuncAttributeMaxDynamicSharedMemorySize, SM_BYTES);

    // weight prep: transpose to [N,K] + bf16 round + K32-permute
    k_prepB<<<dim3(KW / 32, KW / 32), dim3(32, 8)>>>(k2w, Bp2, KW);
    k_prepB<<<dim3(N3 / 32, KW / 32), dim3(32, 8)>>>(k3w, Bp3, N3);

    // edge MLP
    k_mlp1<<<NE * 4, 256>>>(ea, k1w, k1b, r1);
    dim3 g2(KW / 256, (NE + 127) / 128);   // x = N-blocks (fast) for L2 A/B reuse
    dim3 g3(N3 / 256, (NE + 127) / 128);
    k_gemm<<<g2, 256, SM_BYTES>>>(r1, Bp2, k2b, r2, NE, KW, KW, 1);
    k_gemm<<<g3, 256, SM_BYTES>>>(r2, Bp3, k3b, Wd, NE, N3, KW, 0);

    // degrees
    cudaMemsetAsync(inv, 0, NN * sizeof(float));
    k_deg<<<(NE + 255) / 256, 256>>>(ei, inv);
    k_inv<<<(NN + 255) / 256, 256>>>(inv);

    // initial features
    k_h0<<<(NN * 64) / 256, 256>>>(x, fc1w, fc1b, hA);

    float* hc = hA;
    float* hn = hB;
    for (int d = 0; d < 6; d++) {
        cudaMemsetAsync(agg, 0, (size_t)NN * 64 * sizeof(float));
        k_edge<<<NE / 8, 256>>>(hc, Wd, ei, agg);
        k_update<<<NN / 4, 256>>>(hc, agg, inv, root, cb, hn, d < 5 ? 1 : 0);
        float* tmp = hc; hc = hn; hn = tmp;
    }

    k_final<<<NN / 8, 256>>>(hc, fc2w, fc2b, out);
}

// round 15
// speedup vs baseline: 3.0954x; 1.0269x over previous
#include <cuda_runtime.h>
#include <cuda_bf16.h>
#include <cstdint>

#define NE 100000
#define NN 10000
#define KW 1024
#define N3 4096

// ---- static device scratch (no allocations allowed) ----
__device__ __align__(16) __nv_bfloat16 g_r1[(size_t)NE * KW];   // relu1 [E,1024] bf16 K32-permuted
__device__ __align__(16) __nv_bfloat16 g_r2[(size_t)NE * KW];   // relu2 [E,1024] bf16 K32-permuted
__device__ __align__(16) __nv_bfloat16 g_W[(size_t)NE * N3];    // W_edge [E,64,64] bf16 normal
__device__ __align__(16) __nv_bfloat16 g_Bp2[(size_t)KW * KW];  // k2_w^T [N,K] bf16 K32-permuted
__device__ __align__(16) __nv_bfloat16 g_Bp3[(size_t)N3 * KW];  // k3_w^T [N,K] bf16 K32-permuted
__device__ float g_hA[NN * 64];
__device__ float g_hB[NN * 64];
__device__ float g_agg[NN * 64];
__device__ float g_inv[NN];

// K-permutation within each 32-group for m16n8k16 fragments (proven layout):
// 4-byte unit = 4t + 2q + hi -> thread t reads 16 contiguous bytes covering
// both k-steps of a BK=32 sub-block.
__device__ __forceinline__ int permk32(int k) {
    return (k & ~31) | (((k >> 1) & 3) << 3) | (((k >> 4) & 1) << 2)
         | (((k >> 3) & 1) << 1) | (k & 1);
}

__device__ __forceinline__ void mma_bf16(float* d, const uint32_t* a, const uint32_t* b) {
    asm volatile(
        "mma.sync.aligned.m16n8k16.row.col.f32.bf16.bf16.f32 "
        "{%0,%1,%2,%3}, {%4,%5,%6,%7}, {%8,%9}, {%0,%1,%2,%3};\n"
        : "+f"(d[0]), "+f"(d[1]), "+f"(d[2]), "+f"(d[3])
        : "r"(a[0]), "r"(a[1]), "r"(a[2]), "r"(a[3]), "r"(b[0]), "r"(b[1]));
}

// ---- B prep: transpose [K,N] -> [N,K], bf16 round, K32-permute ----
__global__ void k_prepB(const float* __restrict__ in, __nv_bfloat16* __restrict__ out, int N) {
    __shared__ float tile[32][33];
    int nb = blockIdx.x * 32, kb = blockIdx.y * 32;
    for (int i = threadIdx.y; i < 32; i += 8)
        tile[i][threadIdx.x] = in[(size_t)(kb + i) * N + nb + threadIdx.x];
    __syncthreads();
    for (int i = threadIdx.y; i < 32; i += 8) {
        int n = nb + i, k = kb + threadIdx.x;
        out[(size_t)n * KW + permk32(k)] = __float2bfloat16(tile[threadIdx.x][i]);
    }
}

// ---- layer 1 of edge MLP: [E,6] @ [6,1024] + b, relu, bf16, permuted write ----
__global__ void k_mlp1(const float* __restrict__ ea, const float* __restrict__ w,
                       const float* __restrict__ b, __nv_bfloat16* __restrict__ out) {
    int idx = blockIdx.x * 256 + threadIdx.x;
    int e = idx >> 10, n = idx & 1023;
    const float* a = ea + e * 6;
    float s = b[n];
#pragma unroll
    for (int j = 0; j < 6; j++) s = fmaf(a[j], w[j * KW + n], s);
    out[(size_t)e * KW + permk32(n)] = __float2bfloat16(fmaxf(s, 0.f));
}

// ---- bf16 mma.sync GEMM: C[M,N] = A[M,K] @ Bt[N,K]^T + bias ----
// CTA tile 128x256, 512 threads = 16 warps (4M x 4N) of 32x64 warp tiles.
// BK=64 steps (2 x BK=32 sub-tiles, 64B-pitch conflict-free rows).
// 3 stages x 48KB smem, 1 CTA/SM, 4 warps/SMSP.
// mode 1: relu -> bf16 K32-permuted. mode 0: bf16 normal.
#define STG_BYTES 49152   // A: 2x8KB, B: 2x16KB
#define SM_BYTES  (3 * STG_BYTES)

__global__ __launch_bounds__(512, 1)
void k_gemm(const __nv_bfloat16* __restrict__ A, const __nv_bfloat16* __restrict__ B,
            const float* __restrict__ bias, __nv_bfloat16* __restrict__ C,
            int M, int N, int K, int mode) {
    extern __shared__ __align__(16) char smem[];

    const int tid = threadIdx.x;
    const int warp = tid >> 5, lane = tid & 31;
    const int wm = warp & 3, wn = warp >> 2;      // 4M x 4N warps
    const int g = lane >> 2, t = lane & 3;
    const int bN = blockIdx.x, bM = blockIdx.y;

    const __nv_bfloat16* Ablk = A + (size_t)bM * 128 * K;
    const __nv_bfloat16* Bblk = B + (size_t)bN * 256 * K;

    float acc[2][8][4];
#pragma unroll
    for (int i = 0; i < 2; i++)
#pragma unroll
        for (int j = 0; j < 8; j++)
#pragma unroll
            for (int q = 0; q < 4; q++) acc[i][j][q] = 0.f;

    // load one BK=64 chunk (2 x BK=32 sub-tiles) into stage s
    auto loadChunk = [&](int c, int s) {
        char* stg = smem + s * STG_BYTES;
#pragma unroll
        for (int i = 0; i < 2; i++) {   // A: 2 subs x 128 rows x 4 x 16B = 1024
            int idx = tid + i * 512;
            int sub = idx >> 9, rem = idx & 511;
            int row = rem >> 2, j = rem & 3;
            const __nv_bfloat16* src = Ablk + (size_t)row * K + c * 64 + sub * 32 + j * 8;
            int pr = (bM * 128 + row < M) ? 16 : 0;
            uint32_t da = (uint32_t)__cvta_generic_to_shared(stg + sub * 8192 + row * 64 + j * 16);
            asm volatile("cp.async.cg.shared.global [%0], [%1], 16, %2;\n"
                         :: "r"(da), "l"(src), "r"(pr));
        }
#pragma unroll
        for (int i = 0; i < 4; i++) {   // B: 2 subs x 256 rows x 4 x 16B = 2048
            int idx = tid + i * 512;
            int sub = idx >> 10, rem = idx & 1023;
            int row = rem >> 2, j = rem & 3;
            const __nv_bfloat16* src = Bblk + (size_t)row * K + c * 64 + sub * 32 + j * 8;
            uint32_t da = (uint32_t)__cvta_generic_to_shared(stg + 16384 + sub * 16384 + row * 64 + j * 16);
            asm volatile("cp.async.cg.shared.global [%0], [%1], 16;\n"
                         :: "r"(da), "l"(src));
        }
        asm volatile("cp.async.commit_group;\n");
    };

    const int NCH = K / 64;            // 16
    loadChunk(0, 0);
    loadChunk(1, 1);
    int s = 0, ld = 2;
    for (int c = 0; c < NCH; c++) {
        if (c + 1 < NCH) asm volatile("cp.async.wait_group 1;" ::: "memory");
        else             asm volatile("cp.async.wait_group 0;" ::: "memory");
        __syncthreads();
        if (c + 2 < NCH) loadChunk(c + 2, ld);

        const char* stg = smem + s * STG_BYTES;
#pragma unroll
        for (int u = 0; u < 2; u++) {  // two BK=32 sub-tiles
            const char* As = stg + u * 8192;
            const char* Bs = stg + 16384 + u * 16384;
            uint4 av[2][2];
#pragma unroll
            for (int mt = 0; mt < 2; mt++) {
                int r = wm * 32 + mt * 16;
                av[mt][0] = *(const uint4*)(As + (r + g) * 64 + 16 * t);
                av[mt][1] = *(const uint4*)(As + (r + g + 8) * 64 + 16 * t);
            }
#pragma unroll
            for (int nt = 0; nt < 8; nt++) {
                int cn = wn * 64 + nt * 8 + g;
                uint4 bv = *(const uint4*)(Bs + cn * 64 + 16 * t);
                uint32_t b0[2] = { bv.x, bv.y };
                uint32_t b1[2] = { bv.z, bv.w };
#pragma unroll
                for (int mt = 0; mt < 2; mt++) {
                    uint32_t a0[4] = { av[mt][0].x, av[mt][1].x, av[mt][0].y, av[mt][1].y };
                    uint32_t a1[4] = { av[mt][0].z, av[mt][1].z, av[mt][0].w, av[mt][1].w };
                    mma_bf16(acc[mt][nt], a0, b0);
                    mma_bf16(acc[mt][nt], a1, b1);
                }
            }
        }
        s = (s == 2) ? 0 : s + 1;
        ld = (ld == 2) ? 0 : ld + 1;
    }

    // epilogue: bf16 stores always
#pragma unroll
    for (int mt = 0; mt < 2; mt++) {
#pragma unroll
        for (int nt = 0; nt < 8; nt++) {
            int col = bN * 256 + wn * 64 + nt * 8 + 2 * t;
            float b0 = bias[col], b1 = bias[col + 1];
            int r0 = bM * 128 + wm * 32 + mt * 16 + g;
            int r1 = r0 + 8;
            float v0 = acc[mt][nt][0] + b0, v1 = acc[mt][nt][1] + b1;
            float v2 = acc[mt][nt][2] + b0, v3 = acc[mt][nt][3] + b1;
            int oc;
            if (mode == 1) {           // relu + permuted (even/odd pair stays adjacent)
                v0 = fmaxf(v0, 0.f); v1 = fmaxf(v1, 0.f);
                v2 = fmaxf(v2, 0.f); v3 = fmaxf(v3, 0.f);
                oc = permk32(col);
            } else {
                oc = col;
            }
            __nv_bfloat162 h01 = { __float2bfloat16(v0), __float2bfloat16(v1) };
            __nv_bfloat162 h23 = { __float2bfloat16(v2), __float2bfloat16(v3) };
            if (r0 < M) *(__nv_bfloat162*)(C + (size_t)r0 * N + oc) = h01;
            if (r1 < M) *(__nv_bfloat162*)(C + (size_t)r1 * N + oc) = h23;
        }
    }
}

// ---- in-degree via atomics (edge_index is int32: JAX downcasts int64) ----
__global__ void k_deg(const int* __restrict__ ei, float* __restrict__ deg) {
    int i = blockIdx.x * 256 + threadIdx.x;
    if (i < NE) atomicAdd(&deg[ei[NE + i]], 1.f);
}
__global__ void k_inv(float* __restrict__ deg) {
    int n = blockIdx.x * 256 + threadIdx.x;
    if (n < NN) { float d = deg[n]; deg[n] = (d > 0.f) ? (1.f / d) : 0.f; }
}

// ---- h0 = x @ fc1_w + fc1_b (IN_WIDTH = 1) ----
__global__ void k_h0(const float* __restrict__ x, const float* __restrict__ w,
                     const float* __restrict__ b, float* __restrict__ h) {
    int idx = blockIdx.x * 256 + threadIdx.x;
    int n = idx >> 6, o = idx & 63;
    h[idx] = fmaf(x[n], w[o], b[o]);
}

// ---- per-edge matvec + scatter-add: one warp per edge, bf16x2 W ----
__global__ __launch_bounds__(256)
void k_edge(const float* __restrict__ h, const __nv_bfloat16* __restrict__ W,
            const int* __restrict__ ei, float* __restrict__ agg) {
    int warp = threadIdx.x >> 5, lane = threadIdx.x & 31;
    int e = blockIdx.x * 8 + warp;             // NE divisible by 8
    int src = ei[e], dst = ei[NE + e];
    __shared__ float sh[8][64];
    float2 hv = ((const float2*)(h + (size_t)src * 64))[lane];
    sh[warp][2 * lane] = hv.x;
    sh[warp][2 * lane + 1] = hv.y;
    __syncwarp();
    const uint32_t* Wr = (const uint32_t*)(W + (size_t)e * 4096);
    float m0 = 0.f, m1 = 0.f;
#pragma unroll 16
    for (int c = 0; c < 64; c++) {
        float hc = sh[warp][c];
        uint32_t wv = __ldg(&Wr[c * 32 + lane]);
        float2 wf = __bfloat1622float2(*(__nv_bfloat162*)&wv);
        m0 = fmaf(hc, wf.x, m0);
        m1 = fmaf(hc, wf.y, m1);
    }
    atomicAdd(&agg[dst * 64 + 2 * lane], m0);
    atomicAdd(&agg[dst * 64 + 2 * lane + 1], m1);
}

// ---- h_new = agg*inv_deg + h@root + conv_b (+relu) ----
__global__ void k_update(const float* __restrict__ hin, const float* __restrict__ agg,
                         const float* __restrict__ inv, const float* __restrict__ root,
                         const float* __restrict__ cb, float* __restrict__ hout, int relu) {
    int ni = threadIdx.x >> 6;
    int node = blockIdx.x * 4 + ni;
    int o = threadIdx.x & 63;
    __shared__ float sh[4][64];
    sh[ni][o] = hin[node * 64 + o];
    __syncthreads();
    float acc = fmaf(agg[node * 64 + o], inv[node], cb[o]);
#pragma unroll
    for (int c = 0; c < 64; c++) acc = fmaf(sh[ni][c], root[c * 64 + o], acc);
    if (relu) acc = fmaxf(acc, 0.f);
    hout[node * 64 + o] = acc;
}

// ---- out = h @ fc2_w + fc2_b : one warp per node ----
__global__ void k_final(const float* __restrict__ h, const float* __restrict__ w,
                        const float* __restrict__ b, float* __restrict__ out) {
    int node = blockIdx.x * 8 + (threadIdx.x >> 5);
    int lane = threadIdx.x & 31;
    float v = h[node * 64 + lane] * w[lane] + h[node * 64 + 32 + lane] * w[32 + lane];
#pragma unroll
    for (int s = 16; s > 0; s >>= 1) v += __shfl_xor_sync(0xffffffffu, v, s);
    if (lane == 0) out[node] = v + b[0];
}

extern "C" void kernel_launch(void* const* d_in, const int* in_sizes, int n_in,
                              void* d_out, int out_size) {
    const float* x    = (const float*)d_in[0];
    const int*   ei   = (const int*)d_in[1];     // int32
    const float* ea   = (const float*)d_in[2];
    const float* fc1w = (const float*)d_in[3];
    const float* fc1b = (const float*)d_in[4];
    const float* k1w  = (const float*)d_in[5];
    const float* k1b  = (const float*)d_in[6];
    const float* k2w  = (const float*)d_in[7];
    const float* k2b  = (const float*)d_in[8];
    const float* k3w  = (const float*)d_in[9];
    const float* k3b  = (const float*)d_in[10];
    const float* root = (const float*)d_in[11];
    const float* cb   = (const float*)d_in[12];
    const float* fc2w = (const float*)d_in[13];
    const float* fc2b = (const float*)d_in[14];
    float* out = (float*)d_out;

    __nv_bfloat16 *r1, *r2, *Wd, *Bp2, *Bp3;
    float *hA, *hB, *agg, *inv;
    cudaGetSymbolAddress((void**)&r1,  g_r1);
    cudaGetSymbolAddress((void**)&r2,  g_r2);
    cudaGetSymbolAddress((void**)&Wd,  g_W);
    cudaGetSymbolAddress((void**)&Bp2, g_Bp2);
    cudaGetSymbolAddress((void**)&Bp3, g_Bp3);
    cudaGetSymbolAddress((void**)&hA,  g_hA);
    cudaGetSymbolAddress((void**)&hB,  g_hB);
    cudaGetSymbolAddress((void**)&agg, g_agg);
    cudaGetSymbolAddress((void**)&inv, g_inv);

    cudaFuncSetAttribute(k_gemm, cudaFuncAttributeMaxDynamicSharedMemorySize, SM_BYTES);

    // weight prep: transpose to [N,K] + bf16 round + K32-permute
    k_prepB<<<dim3(KW / 32, KW / 32), dim3(32, 8)>>>(k2w, Bp2, KW);
    k_prepB<<<dim3(N3 / 32, KW / 32), dim3(32, 8)>>>(k3w, Bp3, N3);

    // edge MLP
    k_mlp1<<<NE * 4, 256>>>(ea, k1w, k1b, r1);
    dim3 g2(KW / 256, (NE + 127) / 128);   // x = N-blocks (fast) for L2 A/B reuse
    dim3 g3(N3 / 256, (NE + 127) / 128);
    k_gemm<<<g2, 512, SM_BYTES>>>(r1, Bp2, k2b, r2, NE, KW, KW, 1);
    k_gemm<<<g3, 512, SM_BYTES>>>(r2, Bp3, k3b, Wd, NE, N3, KW, 0);

    // degrees
    cudaMemsetAsync(inv, 0, NN * sizeof(float));
    k_deg<<<(NE + 255) / 256, 256>>>(ei, inv);
    k_inv<<<(NN + 255) / 256, 256>>>(inv);

    // initial features
    k_h0<<<(NN * 64) / 256, 256>>>(x, fc1w, fc1b, hA);

    float* hc = hA;
    float* hn = hB;
    for (int d = 0; d < 6; d++) {
        cudaMemsetAsync(agg, 0, (size_t)NN * 64 * sizeof(float));
        k_edge<<<NE / 8, 256>>>(hc, Wd, ei, agg);
        k_update<<<NN / 4, 256>>>(hc, agg, inv, root, cb, hn, d < 5 ? 1 : 0);
        float* tmp = hc; hc = hn; hn = tmp;
    }

    k_final<<<NN / 8, 256>>>(hc, fc2w, fc2b, out);
}

// round 16
// speedup vs baseline: 3.1139x; 1.0060x over previous
#include <cuda_runtime.h>
#include <cuda_bf16.h>
#include <cstdint>

#define NE 100000
#define NN 10000
#define KW 1024
#define N3 4096

// ---- static device scratch (no allocations allowed) ----
__device__ __align__(16) __nv_bfloat16 g_r1[(size_t)NE * KW];   // relu1 [E,1024] bf16 K32-permuted
__device__ __align__(16) __nv_bfloat16 g_r2[(size_t)NE * KW];   // relu2 [E,1024] bf16 K32-permuted
__device__ __align__(16) __nv_bfloat16 g_W[(size_t)NE * N3];    // W_edge [E,64,64] bf16 normal
__device__ __align__(16) __nv_bfloat16 g_Bp2[(size_t)KW * KW];  // k2_w^T [N,K] bf16 K32-permuted
__device__ __align__(16) __nv_bfloat16 g_Bp3[(size_t)N3 * KW];  // k3_w^T [N,K] bf16 K32-permuted
__device__ float g_hA[NN * 64];
__device__ float g_hB[NN * 64];
__device__ float g_agg[NN * 64];
__device__ float g_inv[NN];

// K-permutation within each 32-group for m16n8k16 fragments (proven layout):
// 4-byte unit = 4t + 2q + hi -> thread t reads 16 contiguous bytes covering
// both k-steps of a BK=32 sub-block.
__device__ __forceinline__ int permk32(int k) {
    return (k & ~31) | (((k >> 1) & 3) << 3) | (((k >> 4) & 1) << 2)
         | (((k >> 3) & 1) << 1) | (k & 1);
}

__device__ __forceinline__ void mma_bf16(float* d,
                                         uint32_t a0, uint32_t a1, uint32_t a2, uint32_t a3,
                                         uint32_t b0, uint32_t b1) {
    asm volatile(
        "mma.sync.aligned.m16n8k16.row.col.f32.bf16.bf16.f32 "
        "{%0,%1,%2,%3}, {%4,%5,%6,%7}, {%8,%9}, {%0,%1,%2,%3};\n"
        : "+f"(d[0]), "+f"(d[1]), "+f"(d[2]), "+f"(d[3])
        : "r"(a0), "r"(a1), "r"(a2), "r"(a3), "r"(b0), "r"(b1));
}

// ---- B prep: transpose [K,N] -> [N,K], bf16 round, K32-permute ----
__global__ void k_prepB(const float* __restrict__ in, __nv_bfloat16* __restrict__ out, int N) {
    __shared__ float tile[32][33];
    int nb = blockIdx.x * 32, kb = blockIdx.y * 32;
    for (int i = threadIdx.y; i < 32; i += 8)
        tile[i][threadIdx.x] = in[(size_t)(kb + i) * N + nb + threadIdx.x];
    __syncthreads();
    for (int i = threadIdx.y; i < 32; i += 8) {
        int n = nb + i, k = kb + threadIdx.x;
        out[(size_t)n * KW + permk32(k)] = __float2bfloat16(tile[threadIdx.x][i]);
    }
}

// ---- layer 1 of edge MLP: [E,6] @ [6,1024] + b, relu, bf16, permuted write ----
__global__ void k_mlp1(const float* __restrict__ ea, const float* __restrict__ w,
                       const float* __restrict__ b, __nv_bfloat16* __restrict__ out) {
    int idx = blockIdx.x * 256 + threadIdx.x;
    int e = idx >> 10, n = idx & 1023;
    const float* a = ea + e * 6;
    float s = b[n];
#pragma unroll
    for (int j = 0; j < 6; j++) s = fmaf(a[j], w[j * KW + n], s);
    out[(size_t)e * KW + permk32(n)] = __float2bfloat16(fmaxf(s, 0.f));
}

// ---- bf16 mma.sync GEMM: C[M,N] = A[M,K] @ Bt[N,K]^T + bias ----
// CTA tile 128x256, 512 threads = 16 warps (4M x 4N) of 32x64 warp tiles.
// K fixed at 1024: NCH=16 compile-time. 4 stages, COMPILE-TIME stage rotation
// (inner 4-step unroll) so all smem addresses fold to base+imm.
// mode 1: relu -> bf16 K32-permuted. mode 0: bf16 normal.
#define STG_BYTES 49152   // A: 2x8KB, B: 2x16KB
#define SM_BYTES  (4 * STG_BYTES + 1024)
#define NCH 16

__global__ __launch_bounds__(512, 1)
void k_gemm(const __nv_bfloat16* __restrict__ A, const __nv_bfloat16* __restrict__ B,
            const float* __restrict__ bias, __nv_bfloat16* __restrict__ C,
            int M, int N, int mode) {
    extern __shared__ __align__(16) char smem[];
    const int K = KW;

    const int tid = threadIdx.x;
    const int warp = tid >> 5, lane = tid & 31;
    const int wm = warp & 3, wn = warp >> 2;      // 4M x 4N warps
    const int g = lane >> 2, t = lane & 3;
    const int bN = blockIdx.x, bM = blockIdx.y;

    const __nv_bfloat16* Ablk = A + (size_t)bM * 128 * K;
    const __nv_bfloat16* Bblk = B + (size_t)bN * 256 * K;

    // stage bias in smem (read in epilogue via LDS)
    float* sbias = (float*)(smem + 4 * STG_BYTES);
    if (tid < 256) sbias[tid] = bias[bN * 256 + tid];

    float acc[2][8][4];
#pragma unroll
    for (int i = 0; i < 2; i++)
#pragma unroll
        for (int j = 0; j < 8; j++)
#pragma unroll
            for (int q = 0; q < 4; q++) acc[i][j][q] = 0.f;

    // load one BK=64 chunk (2 x BK=32 sub-tiles) into stage at 'stg'
    auto loadChunk = [&](int c, char* stg) {
#pragma unroll
        for (int i = 0; i < 2; i++) {   // A: 2 subs x 128 rows x 4 x 16B = 1024
            int idx = tid + i * 512;
            int sub = idx >> 9, rem = idx & 511;
            int row = rem >> 2, j = rem & 3;
            const __nv_bfloat16* src = Ablk + (size_t)row * K + c * 64 + sub * 32 + j * 8;
            int pr = (bM * 128 + row < M) ? 16 : 0;
            uint32_t da = (uint32_t)__cvta_generic_to_shared(stg + sub * 8192 + row * 64 + j * 16);
            asm volatile("cp.async.cg.shared.global [%0], [%1], 16, %2;\n"
                         :: "r"(da), "l"(src), "r"(pr));
        }
#pragma unroll
        for (int i = 0; i < 4; i++) {   // B: 2 subs x 256 rows x 4 x 16B = 2048
            int idx = tid + i * 512;
            int sub = idx >> 10, rem = idx & 1023;
            int row = rem >> 2, j = rem & 3;
            const __nv_bfloat16* src = Bblk + (size_t)row * K + c * 64 + sub * 32 + j * 8;
            uint32_t da = (uint32_t)__cvta_generic_to_shared(stg + 16384 + sub * 16384 + row * 64 + j * 16);
            asm volatile("cp.async.cg.shared.global [%0], [%1], 16;\n"
                         :: "r"(da), "l"(src));
        }
        asm volatile("cp.async.commit_group;\n");
    };

    // compute one BK=64 chunk from stage at 'stg'
    auto computeChunk = [&](const char* stg) {
#pragma unroll
        for (int u = 0; u < 2; u++) {
            const char* As = stg + u * 8192;
            const char* Bs = stg + 16384 + u * 16384;
            uint4 a0[2], a1[2];
#pragma unroll
            for (int mt = 0; mt < 2; mt++) {
                int r = wm * 32 + mt * 16;
                a0[mt] = *(const uint4*)(As + (r + g) * 64 + 16 * t);
                a1[mt] = *(const uint4*)(As + (r + g + 8) * 64 + 16 * t);
            }
#pragma unroll
            for (int nt = 0; nt < 8; nt++) {
                uint4 bv = *(const uint4*)(Bs + (wn * 64 + nt * 8 + g) * 64 + 16 * t);
#pragma unroll
                for (int mt = 0; mt < 2; mt++) {
                    mma_bf16(acc[mt][nt], a0[mt].x, a1[mt].x, a0[mt].y, a1[mt].y, bv.x, bv.y);
                    mma_bf16(acc[mt][nt], a0[mt].z, a1[mt].z, a0[mt].w, a1[mt].w, bv.z, bv.w);
                }
            }
        }
    };

    loadChunk(0, smem);
    loadChunk(1, smem + STG_BYTES);
    loadChunk(2, smem + 2 * STG_BYTES);

#pragma unroll 1
    for (int c0 = 0; c0 < NCH; c0 += 4) {
#pragma unroll
        for (int ss = 0; ss < 4; ss++) {       // ss compile-time after unroll
            int c = c0 + ss;
            if (c <= NCH - 3)      asm volatile("cp.async.wait_group 2;" ::: "memory");
            else if (c == NCH - 2) asm volatile("cp.async.wait_group 1;" ::: "memory");
            else                   asm volatile("cp.async.wait_group 0;" ::: "memory");
            __syncthreads();
            if (c + 3 < NCH) loadChunk(c + 3, smem + ((ss + 3) & 3) * STG_BYTES);
            computeChunk(smem + ss * STG_BYTES);
        }
    }

    // epilogue: bf16 stores always, bias from smem
#pragma unroll
    for (int mt = 0; mt < 2; mt++) {
#pragma unroll
        for (int nt = 0; nt < 8; nt++) {
            int lc = wn * 64 + nt * 8 + 2 * t;
            int col = bN * 256 + lc;
            float b0 = sbias[lc], b1 = sbias[lc + 1];
            int r0 = bM * 128 + wm * 32 + mt * 16 + g;
            int r1 = r0 + 8;
            float v0 = acc[mt][nt][0] + b0, v1 = acc[mt][nt][1] + b1;
            float v2 = acc[mt][nt][2] + b0, v3 = acc[mt][nt][3] + b1;
            int oc;
            if (mode == 1) {           // relu + permuted (even/odd pair stays adjacent)
                v0 = fmaxf(v0, 0.f); v1 = fmaxf(v1, 0.f);
                v2 = fmaxf(v2, 0.f); v3 = fmaxf(v3, 0.f);
                oc = permk32(col);
            } else {
                oc = col;
            }
            __nv_bfloat162 h01 = { __float2bfloat16(v0), __float2bfloat16(v1) };
            __nv_bfloat162 h23 = { __float2bfloat16(v2), __float2bfloat16(v3) };
            if (r0 < M) *(__nv_bfloat162*)(C + (size_t)r0 * N + oc) = h01;
            if (r1 < M) *(__nv_bfloat162*)(C + (size_t)r1 * N + oc) = h23;
        }
    }
}

// ---- in-degree via atomics (edge_index is int32: JAX downcasts int64) ----
__global__ void k_deg(const int* __restrict__ ei, float* __restrict__ deg) {
    int i = blockIdx.x * 256 + threadIdx.x;
    if (i < NE) atomicAdd(&deg[ei[NE + i]], 1.f);
}
__global__ void k_inv(float* __restrict__ deg) {
    int n = blockIdx.x * 256 + threadIdx.x;
    if (n < NN) { float d = deg[n]; deg[n] = (d > 0.f) ? (1.f / d) : 0.f; }
}

// ---- h0 = x @ fc1_w + fc1_b (IN_WIDTH = 1) ----
__global__ void k_h0(const float* __restrict__ x, const float* __restrict__ w,
                     const float* __restrict__ b, float* __restrict__ h) {
    int idx = blockIdx.x * 256 + threadIdx.x;
    int n = idx >> 6, o = idx & 63;
    h[idx] = fmaf(x[n], w[o], b[o]);
}

// ---- per-edge matvec + scatter-add: one warp per edge, bf16x2 W ----
__global__ __launch_bounds__(256)
void k_edge(const float* __restrict__ h, const __nv_bfloat16* __restrict__ W,
            const int* __restrict__ ei, float* __restrict__ agg) {
    int warp = threadIdx.x >> 5, lane = threadIdx.x & 31;
    int e = blockIdx.x * 8 + warp;             // NE divisible by 8
    int src = ei[e], dst = ei[NE + e];
    __shared__ float sh[8][64];
    float2 hv = ((const float2*)(h + (size_t)src * 64))[lane];
    sh[warp][2 * lane] = hv.x;
    sh[warp][2 * lane + 1] = hv.y;
    __syncwarp();
    const uint32_t* Wr = (const uint32_t*)(W + (size_t)e * 4096);
    float m0 = 0.f, m1 = 0.f;
#pragma unroll 16
    for (int c = 0; c < 64; c++) {
        float hc = sh[warp][c];
        uint32_t wv = __ldg(&Wr[c * 32 + lane]);
        float2 wf = __bfloat1622float2(*(__nv_bfloat162*)&wv);
        m0 = fmaf(hc, wf.x, m0);
        m1 = fmaf(hc, wf.y, m1);
    }
    atomicAdd(&agg[dst * 64 + 2 * lane], m0);
    atomicAdd(&agg[dst * 64 + 2 * lane + 1], m1);
}

// ---- h_new = agg*inv_deg + h@root + conv_b (+relu) ----
__global__ void k_update(const float* __restrict__ hin, const float* __restrict__ agg,
                         const float* __restrict__ inv, const float* __restrict__ root,
                         const float* __restrict__ cb, float* __restrict__ hout, int relu) {
    int ni = threadIdx.x >> 6;
    int node = blockIdx.x * 4 + ni;
    int o = threadIdx.x & 63;
    __shared__ float sh[4][64];
    sh[ni][o] = hin[node * 64 + o];
    __syncthreads();
    float acc = fmaf(agg[node * 64 + o], inv[node], cb[o]);
#pragma unroll
    for (int c = 0; c < 64; c++) acc = fmaf(sh[ni][c], root[c * 64 + o], acc);
    if (relu) acc = fmaxf(acc, 0.f);
    hout[node * 64 + o] = acc;
}

// ---- out = h @ fc2_w + fc2_b : one warp per node ----
__global__ void k_final(const float* __restrict__ h, const float* __restrict__ w,
                        const float* __restrict__ b, float* __restrict__ out) {
    int node = blockIdx.x * 8 + (threadIdx.x >> 5);
    int lane = threadIdx.x & 31;
    float v = h[node * 64 + lane] * w[lane] + h[node * 64 + 32 + lane] * w[32 + lane];
#pragma unroll
    for (int s = 16; s > 0; s >>= 1) v += __shfl_xor_sync(0xffffffffu, v, s);
    if (lane == 0) out[node] = v + b[0];
}

extern "C" void kernel_launch(void* const* d_in, const int* in_sizes, int n_in,
                              void* d_out, int out_size) {
    const float* x    = (const float*)d_in[0];
    const int*   ei   = (const int*)d_in[1];     // int32
    const float* ea   = (const float*)d_in[2];
    const float* fc1w = (const float*)d_in[3];
    const float* fc1b = (const float*)d_in[4];
    const float* k1w  = (const float*)d_in[5];
    const float* k1b  = (const float*)d_in[6];
    const float* k2w  = (const float*)d_in[7];
    const float* k2b  = (const float*)d_in[8];
    const float* k3w  = (const float*)d_in[9];
    const float* k3b  = (const float*)d_in[10];
    const float* root = (const float*)d_in[11];
    const float* cb   = (const float*)d_in[12];
    const float* fc2w = (const float*)d_in[13];
    const float* fc2b = (const float*)d_in[14];
    float* out = (float*)d_out;

    __nv_bfloat16 *r1, *r2, *Wd, *Bp2, *Bp3;
    float *hA, *hB, *agg, *inv;
    cudaGetSymbolAddress((void**)&r1,  g_r1);
    cudaGetSymbolAddress((void**)&r2,  g_r2);
    cudaGetSymbolAddress((void**)&Wd,  g_W);
    cudaGetSymbolAddress((void**)&Bp2, g_Bp2);
    cudaGetSymbolAddress((void**)&Bp3, g_Bp3);
    cudaGetSymbolAddress((void**)&hA,  g_hA);
    cudaGetSymbolAddress((void**)&hB,  g_hB);
    cudaGetSymbolAddress((void**)&agg, g_agg);
    cudaGetSymbolAddress((void**)&inv, g_inv);

    cudaFuncSetAttribute(k_gemm, cudaFuncAttributeMaxDynamicSharedMemorySize, SM_BYTES);

    // weight prep: transpose to [N,K] + bf16 round + K32-permute
    k_prepB<<<dim3(KW / 32, KW / 32), dim3(32, 8)>>>(k2w, Bp2, KW);
    k_prepB<<<dim3(N3 / 32, KW / 32), dim3(32, 8)>>>(k3w, Bp3, N3);

    // edge MLP
    k_mlp1<<<NE * 4, 256>>>(ea, k1w, k1b, r1);
    dim3 g2(KW / 256, (NE + 127) / 128);   // x = N-blocks (fast) for L2 A/B reuse
    dim3 g3(N3 / 256, (NE + 127) / 128);
    k_gemm<<<g2, 512, SM_BYTES>>>(r1, Bp2, k2b, r2, NE, KW, 1);
    k_gemm<<<g3, 512, SM_BYTES>>>(r2, Bp3, k3b, Wd, NE, N3, 0);

    // degrees
    cudaMemsetAsync(inv, 0, NN * sizeof(float));
    k_deg<<<(NE + 255) / 256, 256>>>(ei, inv);
    k_inv<<<(NN + 255) / 256, 256>>>(inv);

    // initial features
    k_h0<<<(NN * 64) / 256, 256>>>(x, fc1w, fc1b, hA);

    float* hc = hA;
    float* hn = hB;
    for (int d = 0; d < 6; d++) {
        cudaMemsetAsync(agg, 0, (size_t)NN * 64 * sizeof(float));
        k_edge<<<NE / 8, 256>>>(hc, Wd, ei, agg);
        k_update<<<NN / 4, 256>>>(hc, agg, inv, root, cb, hn, d < 5 ? 1 : 0);
        float* tmp = hc; hc = hn; hn = tmp;
    }

    k_final<<<NN / 8, 256>>>(hc, fc2w, fc2b, out);
}